// round 1
// baseline (speedup 1.0000x reference)
#include <cuda_runtime.h>
#include <cstdint>
#include <cstdio>

// ---------------- problem constants ----------------
#define BATCH 32
#define SEQ   2048
#define DIN   1024
#define DMODEL 512
#define NHEAD 8
#define DHEAD 64
#define NCULT 19
#define NMORAL 10
#define NROWS (BATCH*SEQ)   // 65536

// ---------------- scratch (device globals; no allocation allowed) ----------------
__device__ float g_Q1[(size_t)NROWS*1024];    // 256MB: Q1c|Q1m, later reused for Q2c|Q2m
__device__ float g_AV1[(size_t)NROWS*1024];   // 256MB: AV1c|AV1m
__device__ float g_Wf1[1024*1024];            // [DIN, 1024] = [W_lin@c_Wq | W_lin@m_Wq]
__device__ float g_bf1[1024];
__device__ float g_Wf2c[512*512];             // c_Wo @ c_Wq
__device__ float g_Wf2m[512*512];
__device__ float g_bf2c[512];
__device__ float g_bf2m[512];
__device__ float g_Kc[NCULT*512],  g_Vc[NCULT*512];
__device__ float g_Km[NMORAL*512], g_Vm[NMORAL*512];
__device__ float g_pmsum[BATCH];
__device__ float g_part[2][BATCH][16][512];   // per-block partial sums of AV2

// ===================================================================
// TF32 tensor-core GEMM: C[M,N] = A[M,K] @ B[K,N] (+bias per column)
// 128x128 block tile, BK=16, 256 threads (8 warps, 2x4), warp tile 64x32
// double-buffered cp.async, conflict-free padded smem
// ===================================================================
#define BM 128
#define BN 128
#define BKT 16
#define BKP 20    // A smem stride (floats): row stride ≡ 20 mod 32 -> conflict free
#define BNP 136   // B smem stride (floats): row stride ≡ 8  mod 32 -> conflict free

__global__ __launch_bounds__(256, 2)
void gemm_tf32(const float* __restrict__ A, int lda,
               const float* __restrict__ B, int ldb,
               float* __restrict__ C, int ldc,
               const float* __restrict__ bias,
               int Ktiles)
{
    __shared__ float As[2][BM][BKP];
    __shared__ float Bs[2][BKT][BNP];

    const int tid  = threadIdx.x;
    const int warp = tid >> 5;
    const int lane = tid & 31;
    const int wm = warp >> 2;   // 0..1
    const int wn = warp & 3;    // 0..3
    const int m0 = blockIdx.y * BM;
    const int n0 = blockIdx.x * BN;

    float acc[4][4][4];
#pragma unroll
    for (int i = 0; i < 4; i++)
#pragma unroll
        for (int j = 0; j < 4; j++)
#pragma unroll
            for (int r = 0; r < 4; r++) acc[i][j][r] = 0.f;

    auto loadA = [&](int stage, int kt) {
        const int k0 = kt * BKT;
#pragma unroll
        for (int t = 0; t < 2; t++) {
            int i   = tid + t * 256;       // 0..511 float4 slots
            int row = i >> 2;              // 0..127
            int k4  = i & 3;               // 0..3
            const float* src = A + (size_t)(m0 + row) * lda + k0 + k4 * 4;
            uint32_t dst = (uint32_t)__cvta_generic_to_shared(&As[stage][row][k4 * 4]);
            asm volatile("cp.async.cg.shared.global [%0], [%1], 16;\n" :: "r"(dst), "l"(src));
        }
    };
    auto loadB = [&](int stage, int kt) {
        const int k0 = kt * BKT;
#pragma unroll
        for (int t = 0; t < 2; t++) {
            int i   = tid + t * 256;       // 0..511
            int row = i >> 5;              // 0..15
            int n4  = i & 31;              // 0..31
            const float* src = B + (size_t)(k0 + row) * ldb + n0 + n4 * 4;
            uint32_t dst = (uint32_t)__cvta_generic_to_shared(&Bs[stage][row][n4 * 4]);
            asm volatile("cp.async.cg.shared.global [%0], [%1], 16;\n" :: "r"(dst), "l"(src));
        }
    };

    loadA(0, 0); loadB(0, 0);
    asm volatile("cp.async.commit_group;\n");

    for (int kt = 0; kt < Ktiles; kt++) {
        const int cur = kt & 1;
        if (kt + 1 < Ktiles) {
            loadA(cur ^ 1, kt + 1); loadB(cur ^ 1, kt + 1);
            asm volatile("cp.async.commit_group;\n");
            asm volatile("cp.async.wait_group 1;\n");
        } else {
            asm volatile("cp.async.wait_group 0;\n");
        }
        __syncthreads();

#pragma unroll
        for (int ks = 0; ks < 2; ks++) {
            uint32_t a[4][4], b[4][2];
            const int kc = ks * 8 + (lane & 3);
            const int rr = wm * 64 + (lane >> 2);
#pragma unroll
            for (int mt = 0; mt < 4; mt++) {
                a[mt][0] = __float_as_uint(As[cur][rr + mt * 16][kc]);
                a[mt][1] = __float_as_uint(As[cur][rr + mt * 16 + 8][kc]);
                a[mt][2] = __float_as_uint(As[cur][rr + mt * 16][kc + 4]);
                a[mt][3] = __float_as_uint(As[cur][rr + mt * 16 + 8][kc + 4]);
            }
            const int cc = wn * 32 + (lane >> 2);
#pragma unroll
            for (int nt = 0; nt < 4; nt++) {
                b[nt][0] = __float_as_uint(Bs[cur][kc - (lane & 3) + (lane & 3)][0]); // placeholder avoid
                b[nt][0] = __float_as_uint(Bs[cur][ks * 8 + (lane & 3)][cc + nt * 8]);
                b[nt][1] = __float_as_uint(Bs[cur][ks * 8 + (lane & 3) + 4][cc + nt * 8]);
            }
#pragma unroll
            for (int mt = 0; mt < 4; mt++)
#pragma unroll
                for (int nt = 0; nt < 4; nt++) {
                    asm volatile(
                        "mma.sync.aligned.m16n8k8.row.col.f32.tf32.tf32.f32 "
                        "{%0,%1,%2,%3}, {%4,%5,%6,%7}, {%8,%9}, {%0,%1,%2,%3};\n"
                        : "+f"(acc[mt][nt][0]), "+f"(acc[mt][nt][1]),
                          "+f"(acc[mt][nt][2]), "+f"(acc[mt][nt][3])
                        : "r"(a[mt][0]), "r"(a[mt][1]), "r"(a[mt][2]), "r"(a[mt][3]),
                          "r"(b[nt][0]), "r"(b[nt][1]));
                }
        }
        __syncthreads();
    }

    // epilogue
#pragma unroll
    for (int mt = 0; mt < 4; mt++) {
        const int grow = m0 + wm * 64 + mt * 16 + (lane >> 2);
#pragma unroll
        for (int nt = 0; nt < 4; nt++) {
            const int gcol = n0 + wn * 32 + nt * 8 + (lane & 3) * 2;
            float b0 = 0.f, b1 = 0.f;
            if (bias) { b0 = bias[gcol]; b1 = bias[gcol + 1]; }
            float2 v01 = make_float2(acc[mt][nt][0] + b0, acc[mt][nt][1] + b1);
            float2 v23 = make_float2(acc[mt][nt][2] + b0, acc[mt][nt][3] + b1);
            *(float2*)&C[(size_t)grow * ldc + gcol]       = v01;
            *(float2*)&C[(size_t)(grow + 8) * ldc + gcol] = v23;
        }
    }
}

// ===================================================================
// Attention: per row (b,s): for each head, softmax_k(q·k/8 + kmask[b,k]) @ V.
// (query-side additive masks cancel in softmax.)
// Block = 128 rows, 256 threads; warp = 16 rows; lane = (row_in_16, half)
// covering 32 dims of the current head. K/V staged in dynamic smem.
// ACC mode: reduce over the block's rows into g_part (deterministic).
// ===================================================================
template<int NK, bool ACC>
__global__ void attn_kernel(const float* __restrict__ Q, int ldq, int qoff,
                            const float* __restrict__ Kh, const float* __restrict__ Vh,
                            const int* __restrict__ kmask,
                            float* __restrict__ OUT, int ldo, int ooff,
                            float* __restrict__ PART)
{
    extern __shared__ float sh[];
    float* Ks = sh;
    float* Vs = sh + NK * 512;
    __shared__ float kmf[32];
    __shared__ float wacc[ACC ? 8 : 1][ACC ? 512 : 1];

    const int tid  = threadIdx.x;
    const int row0 = blockIdx.x * 128;
    const int b    = row0 >> 11;          // 2048 rows per batch

    for (int i = tid; i < NK * 512; i += 256) { Ks[i] = Kh[i]; Vs[i] = Vh[i]; }
    if (tid < NK) kmf[tid] = (float)kmask[b * NK + tid];
    if (ACC) for (int i = tid; i < 8 * 512; i += 256) ((float*)wacc)[i] = 0.f;
    __syncthreads();

    const int warp = tid >> 5, lane = tid & 31;
    const int r = lane >> 1, half = lane & 1;
    const int row = row0 + warp * 16 + r;
    const float* qrow = Q + (size_t)row * ldq + qoff;

#pragma unroll 1
    for (int h = 0; h < NHEAD; h++) {
        const int doff = h * 64 + half * 32;
        float q[32];
        const float* qp = qrow + doff;
#pragma unroll
        for (int j4 = 0; j4 < 8; j4++) {
            float4 v = *(const float4*)(qp + j4 * 4);
            q[j4*4+0] = v.x; q[j4*4+1] = v.y; q[j4*4+2] = v.z; q[j4*4+3] = v.w;
        }
        float w[NK];
        float mx = -1e30f;
#pragma unroll
        for (int k = 0; k < NK; k++) {
            const float* kp = Ks + k * 512 + doff;
            float d = 0.f;
#pragma unroll
            for (int j4 = 0; j4 < 8; j4++) {
                float4 kv = *(const float4*)(kp + j4 * 4);
                d += q[j4*4+0]*kv.x + q[j4*4+1]*kv.y + q[j4*4+2]*kv.z + q[j4*4+3]*kv.w;
            }
            d += __shfl_xor_sync(0xffffffffu, d, 1);
            float lg = d * 0.125f + kmf[k];
            w[k] = lg;
            mx = fmaxf(mx, lg);
        }
        float s = 0.f;
#pragma unroll
        for (int k = 0; k < NK; k++) { w[k] = __expf(w[k] - mx); s += w[k]; }
        const float inv = 1.f / s;

        float o[32];
#pragma unroll
        for (int j = 0; j < 32; j++) o[j] = 0.f;
#pragma unroll
        for (int k = 0; k < NK; k++) {
            const float wk = w[k];
            const float* vp = Vs + k * 512 + doff;
#pragma unroll
            for (int j4 = 0; j4 < 8; j4++) {
                float4 vv = *(const float4*)(vp + j4 * 4);
                o[j4*4+0] += wk * vv.x; o[j4*4+1] += wk * vv.y;
                o[j4*4+2] += wk * vv.z; o[j4*4+3] += wk * vv.w;
            }
        }
#pragma unroll
        for (int j = 0; j < 32; j++) o[j] *= inv;

        if (!ACC) {
            float* op = OUT + (size_t)row * ldo + ooff + doff;
#pragma unroll
            for (int j4 = 0; j4 < 8; j4++)
                *(float4*)(op + j4 * 4) = make_float4(o[j4*4+0], o[j4*4+1], o[j4*4+2], o[j4*4+3]);
        } else {
            // reduce the 16 rows of this warp (lanes differing in r-bits)
#pragma unroll
            for (int st = 2; st < 32; st <<= 1)
#pragma unroll
                for (int j = 0; j < 32; j++) o[j] += __shfl_xor_sync(0xffffffffu, o[j], st);
            if (r == 0) {
#pragma unroll
                for (int j = 0; j < 32; j++) wacc[warp][doff + j] += o[j];
            }
        }
    }

    if (ACC) {
        __syncthreads();
        float* dst = PART + ((size_t)b * 16 + (blockIdx.x & 15)) * 512;
        for (int i = tid; i < 512; i += 256) {
            float s = 0.f;
#pragma unroll
            for (int w8 = 0; w8 < 8; w8++) s += wacc[w8][i];
            dst[i] = s;
        }
    }
}

// ===================================================================
// Small prep: K/V head tables (table@Wk+bk etc.) and folded bias rows.
// One block = one output row of 512; exact fp32.
// ===================================================================
__global__ void prep_rows(const float* __restrict__ ctab, const float* __restrict__ mtab,
                          const float* __restrict__ cWk, const float* __restrict__ cbk,
                          const float* __restrict__ cWv, const float* __restrict__ cbv,
                          const float* __restrict__ mWk, const float* __restrict__ mbk,
                          const float* __restrict__ mWv, const float* __restrict__ mbv,
                          const float* __restrict__ b_lin,
                          const float* __restrict__ cWq, const float* __restrict__ cbq,
                          const float* __restrict__ mWq, const float* __restrict__ mbq,
                          const float* __restrict__ cbo, const float* __restrict__ mbo)
{
    const int id = blockIdx.x;
    const float* arow; const float* W; const float* bb; float* out;
    if      (id < 19)  { arow = ctab + id * 512;        W = cWk; bb = cbk; out = g_Kc + id * 512; }
    else if (id < 38)  { arow = ctab + (id - 19) * 512; W = cWv; bb = cbv; out = g_Vc + (id - 19) * 512; }
    else if (id < 48)  { arow = mtab + (id - 38) * 512; W = mWk; bb = mbk; out = g_Km + (id - 38) * 512; }
    else if (id < 58)  { arow = mtab + (id - 48) * 512; W = mWv; bb = mbv; out = g_Vm + (id - 48) * 512; }
    else if (id == 58) { arow = b_lin; W = cWq; bb = cbq; out = g_bf1; }
    else if (id == 59) { arow = b_lin; W = mWq; bb = mbq; out = g_bf1 + 512; }
    else if (id == 60) { arow = cbo;   W = cWq; bb = cbq; out = g_bf2c; }
    else               { arow = mbo;   W = mWq; bb = mbq; out = g_bf2m; }

    __shared__ float sA[512];
    const int c = threadIdx.x;
    sA[c] = arow[c];
    __syncthreads();
    float acc = bb[c];
    for (int k = 0; k < 512; k++) acc += sA[k] * W[k * 512 + c];
    out[c] = acc;
}

// pmsum[b] = sum_s embeddings_mask * post_mask
__global__ void pmsum_kernel(const int* __restrict__ em, const int* __restrict__ pmask)
{
    __shared__ int sred[8];
    const int b = blockIdx.x, t = threadIdx.x;
    int cnt = 0;
    for (int s = t; s < SEQ; s += 256) cnt += em[b * SEQ + s] * pmask[b * SEQ + s];
#pragma unroll
    for (int st = 16; st; st >>= 1) cnt += __shfl_xor_sync(0xffffffffu, cnt, st);
    if ((t & 31) == 0) sred[t >> 5] = cnt;
    __syncthreads();
    if (t == 0) { int tot = 0; for (int w = 0; w < 8; w++) tot += sred[w]; g_pmsum[b] = (float)tot; }
}

// final: out_c = (sum_part @ Wo + S*bo)/pmsum ; pooled = out_c - out_m
__global__ void final_kernel(const float* __restrict__ cWo, const float* __restrict__ cbo,
                             const float* __restrict__ mWo, const float* __restrict__ mbo,
                             float* __restrict__ out)
{
    __shared__ float sc[512], sm2[512];
    const int b = blockIdx.x, c = threadIdx.x;
    float a0 = 0.f, a1 = 0.f;
#pragma unroll
    for (int p = 0; p < 16; p++) { a0 += g_part[0][b][p][c]; a1 += g_part[1][b][p][c]; }
    sc[c] = a0; sm2[c] = a1;
    __syncthreads();
    float oc = 0.f, om = 0.f;
    for (int k = 0; k < 512; k++) {
        oc += sc[k]  * cWo[k * 512 + c];
        om += sm2[k] * mWo[k * 512 + c];
    }
    const float invp = 1.f / g_pmsum[b];
    oc = (oc + 2048.f * cbo[c]) * invp;
    om = (om + 2048.f * mbo[c]) * invp;
    out[b * 512 + c] = oc;
    out[BATCH * 512 + b * 512 + c] = oc - om;
}

// ===================================================================
extern "C" void kernel_launch(void* const* d_in, const int* in_sizes, int n_in,
                              void* d_out, int out_size)
{
    const float* emb   = (const float*)d_in[0];
    const int*   emask = (const int*)d_in[1];
    const int*   pmask = (const int*)d_in[2];
    // d_in[3] (frame_mask) cancels in softmax — unused
    const int*   cmask = (const int*)d_in[4];
    const int*   mmask = (const int*)d_in[5];
    const float* W_lin = (const float*)d_in[6];
    const float* b_lin = (const float*)d_in[7];
    const float* ctab  = (const float*)d_in[8];
    const float* mtab  = (const float*)d_in[9];
    const float* cWq = (const float*)d_in[10]; const float* cbq = (const float*)d_in[11];
    const float* cWk = (const float*)d_in[12]; const float* cbk = (const float*)d_in[13];
    const float* cWv = (const float*)d_in[14]; const float* cbv = (const float*)d_in[15];
    const float* cWo = (const float*)d_in[16]; const float* cbo = (const float*)d_in[17];
    const float* mWq = (const float*)d_in[18]; const float* mbq = (const float*)d_in[19];
    const float* mWk = (const float*)d_in[20]; const float* mbk = (const float*)d_in[21];
    const float* mWv = (const float*)d_in[22]; const float* mbv = (const float*)d_in[23];
    const float* mWo = (const float*)d_in[24]; const float* mbo = (const float*)d_in[25];
    float* out = (float*)d_out;

    float *pQ1, *pAV1, *pWf1, *pbf1, *pWf2c, *pWf2m, *pbf2c, *pbf2m;
    float *pKc, *pVc, *pKm, *pVm, *pPart;
    cudaGetSymbolAddress((void**)&pQ1,   g_Q1);
    cudaGetSymbolAddress((void**)&pAV1,  g_AV1);
    cudaGetSymbolAddress((void**)&pWf1,  g_Wf1);
    cudaGetSymbolAddress((void**)&pbf1,  g_bf1);
    cudaGetSymbolAddress((void**)&pWf2c, g_Wf2c);
    cudaGetSymbolAddress((void**)&pWf2m, g_Wf2m);
    cudaGetSymbolAddress((void**)&pbf2c, g_bf2c);
    cudaGetSymbolAddress((void**)&pbf2m, g_bf2m);
    cudaGetSymbolAddress((void**)&pKc,   g_Kc);
    cudaGetSymbolAddress((void**)&pVc,   g_Vc);
    cudaGetSymbolAddress((void**)&pKm,   g_Km);
    cudaGetSymbolAddress((void**)&pVm,   g_Vm);
    cudaGetSymbolAddress((void**)&pPart, g_part);

    const int smemC = NCULT  * 1024 * 4;   // 77824 B
    const int smemM = NMORAL * 1024 * 4;   // 40960 B
    cudaFuncSetAttribute(attn_kernel<NCULT,  false>, cudaFuncAttributeMaxDynamicSharedMemorySize, smemC);
    cudaFuncSetAttribute(attn_kernel<NCULT,  true >, cudaFuncAttributeMaxDynamicSharedMemorySize, smemC);
    cudaFuncSetAttribute(attn_kernel<NMORAL, false>, cudaFuncAttributeMaxDynamicSharedMemorySize, smemM);
    cudaFuncSetAttribute(attn_kernel<NMORAL, true >, cudaFuncAttributeMaxDynamicSharedMemorySize, smemM);

    // small preps (K/V head tables + folded biases) and pmsum
    prep_rows<<<62, 512>>>(ctab, mtab, cWk, cbk, cWv, cbv, mWk, mbk, mWv, mbv,
                           b_lin, cWq, cbq, mWq, mbq, cbo, mbo);
    pmsum_kernel<<<BATCH, 256>>>(emask, pmask);

    // weight folds (tf32 GEMM; small)
    gemm_tf32<<<dim3(4, 8), 256>>>(W_lin, 512, cWq, 512, pWf1,       1024, nullptr, 32); // [1024,512]
    gemm_tf32<<<dim3(4, 8), 256>>>(W_lin, 512, mWq, 512, pWf1 + 512, 1024, nullptr, 32);
    gemm_tf32<<<dim3(4, 4), 256>>>(cWo, 512, cWq, 512, pWf2c, 512, nullptr, 32);         // [512,512]
    gemm_tf32<<<dim3(4, 4), 256>>>(mWo, 512, mWq, 512, pWf2m, 512, nullptr, 32);

    // G1: Q1(c|m) = emb @ Wf1 + bf1   [65536,1024]x[1024,1024]
    gemm_tf32<<<dim3(8, 512), 256>>>(emb, 1024, pWf1, 1024, pQ1, 1024, pbf1, 64);

    // attention layer 1 -> AV1
    attn_kernel<NCULT,  false><<<512, 256, smemC>>>(pQ1, 1024, 0,   pKc, pVc, cmask, pAV1, 1024, 0,   nullptr);
    attn_kernel<NMORAL, false><<<512, 256, smemM>>>(pQ1, 1024, 512, pKm, pVm, mmask, pAV1, 1024, 512, nullptr);

    // G2: Q2 = AV1 @ (Wo@Wq) + fold-bias   (written back into g_Q1 columns)
    gemm_tf32<<<dim3(4, 512), 256>>>(pAV1,       1024, pWf2c, 512, pQ1,       1024, pbf2c, 32);
    gemm_tf32<<<dim3(4, 512), 256>>>(pAV1 + 512, 1024, pWf2m, 512, pQ1 + 512, 1024, pbf2m, 32);

    // attention layer 2 with fused sequence-sum -> g_part
    attn_kernel<NCULT,  true><<<512, 256, smemC>>>(pQ1, 1024, 0,   pKc, pVc, cmask, nullptr, 0, 0, pPart);
    attn_kernel<NMORAL, true><<<512, 256, smemM>>>(pQ1, 1024, 512, pKm, pVm, mmask, nullptr, 0, 0,
                                                   pPart + (size_t)BATCH * 16 * 512);

    // final projection + pooling
    final_kernel<<<BATCH, 512>>>(cWo, cbo, mWo, mbo, out);
}

// round 3
// speedup vs baseline: 1.0257x; 1.0257x over previous
#include <cuda_runtime.h>
#include <cuda_bf16.h>
#include <cstdint>

// ---------------- problem constants ----------------
#define BATCH 32
#define SEQ   2048
#define NHEAD 8
#define NCULT 19
#define NMORAL 10
#define NROWS (BATCH*SEQ)   // 65536

// ---------------- scratch (device globals; no allocation allowed) ----------------
__device__ __nv_bfloat16 g_emb16[(size_t)NROWS*1024];  // 128MB bf16 embeddings
__device__ __nv_bfloat16 g_Q1[(size_t)NROWS*1024];     // 128MB Q1c|Q1m, reused for Q2
__device__ __nv_bfloat16 g_AV1[(size_t)NROWS*1024];    // 128MB AV1c|AV1m
__device__ __nv_bfloat16 g_Wf1T[1024*1024];            // [n][k] = (W_lin@Wq)[k][n], c|m stacked in n
__device__ __nv_bfloat16 g_Wf2cT[512*512];             // [n][k] = (c_Wo@c_Wq)[k][n]
__device__ __nv_bfloat16 g_Wf2mT[512*512];
__device__ float g_bf1[1024];
__device__ float g_bf2c[512];
__device__ float g_bf2m[512];
__device__ float g_Kc[NCULT*512],  g_Vc[NCULT*512];
__device__ float g_Km[NMORAL*512], g_Vm[NMORAL*512];
__device__ float g_pmsum[BATCH];
__device__ float g_part[2][BATCH][16][512];

__device__ __forceinline__ uint32_t smem_u32(const void* p) {
    return (uint32_t)__cvta_generic_to_shared(p);
}
__device__ __forceinline__ void cp_async16(uint32_t dst, const void* src) {
    asm volatile("cp.async.cg.shared.global [%0], [%1], 16;" :: "r"(dst), "l"(src));
}
__device__ __forceinline__ uint32_t sw128(uint32_t b) { return b ^ ((b >> 3) & 0x70u); }

// ===================================================================
// bf16 mma.sync GEMM: C[M,N](bf16) = A[M,K](bf16) @ B^T + fp32 bias
//   B stored [N,K] bf16 (K-major). Tile 128x128, BK=32, 3 stages.
//   256 threads, 8 warps (2x4), warp tile 64x32. ldmatrix-fed fragments.
// ===================================================================
#define GBM 128
#define GBN 128
#define GBK 32
#define STG 3
#define STAGE_B 16384   // A 8KB + B 8KB

__global__ __launch_bounds__(256, 2)
void gemm_bf16(const __nv_bfloat16* __restrict__ A, int lda,
               const __nv_bfloat16* __restrict__ B, int ldb,
               __nv_bfloat16* __restrict__ C, int ldc,
               const float* __restrict__ bias, int KT)
{
    __shared__ __align__(1024) char sm[STG * STAGE_B];
    const uint32_t sbase = smem_u32(sm);

    const int tid  = threadIdx.x;
    const int warp = tid >> 5, lane = tid & 31;
    const int wm = warp >> 2;        // 0..1 -> m offset *64
    const int wn = warp & 3;         // 0..3 -> n offset *32
    const int m0 = blockIdx.y * GBM;
    const int n0 = blockIdx.x * GBN;

    float acc[4][4][4];
#pragma unroll
    for (int i = 0; i < 4; i++)
#pragma unroll
        for (int j = 0; j < 4; j++) {
            acc[i][j][0] = 0.f; acc[i][j][1] = 0.f; acc[i][j][2] = 0.f; acc[i][j][3] = 0.f;
        }

    // cp.async: 512 chunks of 16B per operand per stage, 2 per thread
    auto load_stage = [&](int s, int kt) {
        const uint32_t ab = sbase + s * STAGE_B;
        const uint32_t bb = ab + 8192;
        const __nv_bfloat16* Ag = A + kt * GBK;
        const __nv_bfloat16* Bg = B + kt * GBK;
#pragma unroll
        for (int t = 0; t < 2; t++) {
            int id  = tid + t * 256;
            int row = id >> 2, c = id & 3;
            uint32_t byte = row * 64 + c * 16;
            cp_async16(ab + sw128(byte), Ag + (size_t)(m0 + row) * lda + c * 8);
            cp_async16(bb + sw128(byte), Bg + (size_t)(n0 + row) * ldb + c * 8);
        }
    };

    load_stage(0, 0);
    asm volatile("cp.async.commit_group;");
    load_stage(1, 1);
    asm volatile("cp.async.commit_group;");

    // per-lane ldmatrix row/col components
    const int a_row = lane & 15;                 // row within m16
    const int a_k8  = (lane >> 4) << 3;          // k half select
    const int b_row = (lane & 7) | ((lane >> 4) << 3);   // row within n16
    const int b_k8  = ((lane >> 3) & 1) << 3;    // k half select

    for (int kt = 0; kt < KT; kt++) {
        const int buf = kt % STG;
        asm volatile("cp.async.wait_group 1;");
        __syncthreads();
        if (kt + 2 < KT) load_stage((kt + 2) % STG, kt + 2);
        asm volatile("cp.async.commit_group;");

        const uint32_t aS = sbase + buf * STAGE_B;
        const uint32_t bS = aS + 8192;

#pragma unroll
        for (int kk = 0; kk < 2; kk++) {          // two k16 steps
            uint32_t a[4][4], b[2][4];
#pragma unroll
            for (int mt = 0; mt < 4; mt++) {
                uint32_t byte = (uint32_t)(wm * 64 + mt * 16 + a_row) * 64
                              + (uint32_t)(kk * 16 + a_k8) * 2;
                uint32_t ad = aS + sw128(byte);
                asm volatile(
                    "ldmatrix.sync.aligned.m8n8.x4.shared.b16 {%0,%1,%2,%3}, [%4];"
                    : "=r"(a[mt][0]), "=r"(a[mt][1]), "=r"(a[mt][2]), "=r"(a[mt][3])
                    : "r"(ad));
            }
#pragma unroll
            for (int np = 0; np < 2; np++) {
                uint32_t byte = (uint32_t)(wn * 32 + np * 16 + b_row) * 64
                              + (uint32_t)(kk * 16 + b_k8) * 2;
                uint32_t bd = bS + sw128(byte);
                asm volatile(
                    "ldmatrix.sync.aligned.m8n8.x4.shared.b16 {%0,%1,%2,%3}, [%4];"
                    : "=r"(b[np][0]), "=r"(b[np][1]), "=r"(b[np][2]), "=r"(b[np][3])
                    : "r"(bd));
            }
#pragma unroll
            for (int mt = 0; mt < 4; mt++)
#pragma unroll
                for (int nt = 0; nt < 4; nt++) {
                    const uint32_t b0 = b[nt >> 1][(nt & 1) * 2];
                    const uint32_t b1 = b[nt >> 1][(nt & 1) * 2 + 1];
                    asm volatile(
                        "mma.sync.aligned.m16n8k16.row.col.f32.bf16.bf16.f32 "
                        "{%0,%1,%2,%3}, {%4,%5,%6,%7}, {%8,%9}, {%0,%1,%2,%3};"
                        : "+f"(acc[mt][nt][0]), "+f"(acc[mt][nt][1]),
                          "+f"(acc[mt][nt][2]), "+f"(acc[mt][nt][3])
                        : "r"(a[mt][0]), "r"(a[mt][1]), "r"(a[mt][2]), "r"(a[mt][3]),
                          "r"(b0), "r"(b1));
                }
        }
        __syncthreads();
    }

    // epilogue: bias + bf16 store
#pragma unroll
    for (int mt = 0; mt < 4; mt++) {
        const int r0 = m0 + wm * 64 + mt * 16 + (lane >> 2);
#pragma unroll
        for (int nt = 0; nt < 4; nt++) {
            const int gc = n0 + wn * 32 + nt * 8 + (lane & 3) * 2;
            float bb0 = 0.f, bb1 = 0.f;
            if (bias) { bb0 = bias[gc]; bb1 = bias[gc + 1]; }
            __nv_bfloat162 h0 = __floats2bfloat162_rn(acc[mt][nt][0] + bb0, acc[mt][nt][1] + bb1);
            __nv_bfloat162 h1 = __floats2bfloat162_rn(acc[mt][nt][2] + bb0, acc[mt][nt][3] + bb1);
            *reinterpret_cast<__nv_bfloat162*>(C + (size_t)r0 * ldc + gc)       = h0;
            *reinterpret_cast<__nv_bfloat162*>(C + (size_t)(r0 + 8) * ldc + gc) = h1;
        }
    }
}

// ===================================================================
// fold GEMMs (tf32 mma.sync, exact-ish): all four weight folds in ONE launch.
// Writes bf16 TRANSPOSED output: CT[n][k] = (A@B)[k][n].
// ===================================================================
#define BM 128
#define BN 128
#define BKT 16
#define BKP 20
#define BNP 136

__global__ __launch_bounds__(256, 2)
void fold_gemm(const float* __restrict__ W_lin,
               const float* __restrict__ cWq, const float* __restrict__ mWq,
               const float* __restrict__ cWo, const float* __restrict__ mWo,
               __nv_bfloat16* __restrict__ Wf1T,
               __nv_bfloat16* __restrict__ Wf2cT,
               __nv_bfloat16* __restrict__ Wf2mT)
{
    const int z = blockIdx.z;
    const float* A; const float* B; __nv_bfloat16* CT; int ldt, Mrows;
    if (z == 0)      { A = W_lin; B = cWq; CT = Wf1T;              ldt = 1024; Mrows = 1024; }
    else if (z == 1) { A = W_lin; B = mWq; CT = Wf1T + 512 * 1024; ldt = 1024; Mrows = 1024; }
    else if (z == 2) { A = cWo;   B = cWq; CT = Wf2cT;             ldt = 512;  Mrows = 512; }
    else             { A = mWo;   B = mWq; CT = Wf2mT;             ldt = 512;  Mrows = 512; }
    if (blockIdx.y * BM >= Mrows) return;

    __shared__ float As[2][BM][BKP];
    __shared__ float Bs[2][BKT][BNP];

    const int tid  = threadIdx.x;
    const int warp = tid >> 5;
    const int lane = tid & 31;
    const int wm = warp >> 2;
    const int wn = warp & 3;
    const int m0 = blockIdx.y * BM;
    const int n0 = blockIdx.x * BN;
    const int lda = 512, ldb = 512, Ktiles = 32;

    float acc[4][4][4];
#pragma unroll
    for (int i = 0; i < 4; i++)
#pragma unroll
        for (int j = 0; j < 4; j++)
#pragma unroll
            for (int r = 0; r < 4; r++) acc[i][j][r] = 0.f;

    auto loadA = [&](int stage, int kt) {
        const int k0 = kt * BKT;
#pragma unroll
        for (int t = 0; t < 2; t++) {
            int i = tid + t * 256;
            int row = i >> 2, k4 = i & 3;
            cp_async16(smem_u32(&As[stage][row][k4 * 4]),
                       A + (size_t)(m0 + row) * lda + k0 + k4 * 4);
        }
    };
    auto loadB = [&](int stage, int kt) {
        const int k0 = kt * BKT;
#pragma unroll
        for (int t = 0; t < 2; t++) {
            int i = tid + t * 256;
            int row = i >> 5, n4 = i & 31;
            cp_async16(smem_u32(&Bs[stage][row][n4 * 4]),
                       B + (size_t)(k0 + row) * ldb + n0 + n4 * 4);
        }
    };

    loadA(0, 0); loadB(0, 0);
    asm volatile("cp.async.commit_group;\n");

    for (int kt = 0; kt < Ktiles; kt++) {
        const int cur = kt & 1;
        if (kt + 1 < Ktiles) {
            loadA(cur ^ 1, kt + 1); loadB(cur ^ 1, kt + 1);
            asm volatile("cp.async.commit_group;\n");
            asm volatile("cp.async.wait_group 1;\n");
        } else {
            asm volatile("cp.async.wait_group 0;\n");
        }
        __syncthreads();

#pragma unroll
        for (int ks = 0; ks < 2; ks++) {
            uint32_t a[4][4], b[4][2];
            const int kc = ks * 8 + (lane & 3);
            const int rr = wm * 64 + (lane >> 2);
#pragma unroll
            for (int mt = 0; mt < 4; mt++) {
                a[mt][0] = __float_as_uint(As[cur][rr + mt * 16][kc]);
                a[mt][1] = __float_as_uint(As[cur][rr + mt * 16 + 8][kc]);
                a[mt][2] = __float_as_uint(As[cur][rr + mt * 16][kc + 4]);
                a[mt][3] = __float_as_uint(As[cur][rr + mt * 16 + 8][kc + 4]);
            }
            const int cc = wn * 32 + (lane >> 2);
#pragma unroll
            for (int nt = 0; nt < 4; nt++) {
                b[nt][0] = __float_as_uint(Bs[cur][ks * 8 + (lane & 3)][cc + nt * 8]);
                b[nt][1] = __float_as_uint(Bs[cur][ks * 8 + (lane & 3) + 4][cc + nt * 8]);
            }
#pragma unroll
            for (int mt = 0; mt < 4; mt++)
#pragma unroll
                for (int nt = 0; nt < 4; nt++) {
                    asm volatile(
                        "mma.sync.aligned.m16n8k8.row.col.f32.tf32.tf32.f32 "
                        "{%0,%1,%2,%3}, {%4,%5,%6,%7}, {%8,%9}, {%0,%1,%2,%3};\n"
                        : "+f"(acc[mt][nt][0]), "+f"(acc[mt][nt][1]),
                          "+f"(acc[mt][nt][2]), "+f"(acc[mt][nt][3])
                        : "r"(a[mt][0]), "r"(a[mt][1]), "r"(a[mt][2]), "r"(a[mt][3]),
                          "r"(b[nt][0]), "r"(b[nt][1]));
                }
        }
        __syncthreads();
    }

    // epilogue: transposed bf16 store CT[n][k]
#pragma unroll
    for (int mt = 0; mt < 4; mt++) {
        const int grow = m0 + wm * 64 + mt * 16 + (lane >> 2);
#pragma unroll
        for (int nt = 0; nt < 4; nt++) {
            const int gcol = n0 + wn * 32 + nt * 8 + (lane & 3) * 2;
            CT[(size_t)gcol * ldt + grow]           = __float2bfloat16(acc[mt][nt][0]);
            CT[(size_t)(gcol + 1) * ldt + grow]     = __float2bfloat16(acc[mt][nt][1]);
            CT[(size_t)gcol * ldt + grow + 8]       = __float2bfloat16(acc[mt][nt][2]);
            CT[(size_t)(gcol + 1) * ldt + grow + 8] = __float2bfloat16(acc[mt][nt][3]);
        }
    }
}

// ===================================================================
// fp32 -> bf16 conversion (embeddings)
// ===================================================================
__global__ void conv_bf16_kernel(const float4* __restrict__ in, uint4* __restrict__ out, int n16)
{
    int i = blockIdx.x * blockDim.x + threadIdx.x;
    const int stride = gridDim.x * blockDim.x;
    for (; i < n16; i += stride) {
        float4 a = in[2 * i], b = in[2 * i + 1];
        __nv_bfloat162 h0 = __floats2bfloat162_rn(a.x, a.y);
        __nv_bfloat162 h1 = __floats2bfloat162_rn(a.z, a.w);
        __nv_bfloat162 h2 = __floats2bfloat162_rn(b.x, b.y);
        __nv_bfloat162 h3 = __floats2bfloat162_rn(b.z, b.w);
        out[i] = make_uint4(*reinterpret_cast<uint32_t*>(&h0), *reinterpret_cast<uint32_t*>(&h1),
                            *reinterpret_cast<uint32_t*>(&h2), *reinterpret_cast<uint32_t*>(&h3));
    }
}

// ===================================================================
// Attention (bf16 Q, fp32 K/V in smem).
// ===================================================================
template<int NK, bool ACC>
__global__ void attn_kernel(const __nv_bfloat16* __restrict__ Q, int ldq, int qoff,
                            const float* __restrict__ Kh, const float* __restrict__ Vh,
                            const int* __restrict__ kmask,
                            __nv_bfloat16* __restrict__ OUT, int ldo, int ooff,
                            float* __restrict__ PART)
{
    extern __shared__ float sh[];
    float* Ks = sh;
    float* Vs = sh + NK * 512;
    __shared__ float kmf[32];
    __shared__ float wacc[ACC ? 8 : 1][ACC ? 512 : 1];

    const int tid  = threadIdx.x;
    const int row0 = blockIdx.x * 128;
    const int b    = row0 >> 11;

    for (int i = tid; i < NK * 512; i += 256) { Ks[i] = Kh[i]; Vs[i] = Vh[i]; }
    if (tid < NK) kmf[tid] = (float)kmask[b * NK + tid];
    if (ACC) for (int i = tid; i < 8 * 512; i += 256) ((float*)wacc)[i] = 0.f;
    __syncthreads();

    const int warp = tid >> 5, lane = tid & 31;
    const int r = lane >> 1, half = lane & 1;
    const int row = row0 + warp * 16 + r;
    const __nv_bfloat16* qrow = Q + (size_t)row * ldq + qoff;

#pragma unroll 1
    for (int h = 0; h < NHEAD; h++) {
        const int doff = h * 64 + half * 32;
        float q[32];
        const uint4* q4 = reinterpret_cast<const uint4*>(qrow + doff);
#pragma unroll
        for (int t = 0; t < 4; t++) {
            uint4 u = q4[t];
            uint32_t w4[4] = {u.x, u.y, u.z, u.w};
#pragma unroll
            for (int j = 0; j < 4; j++) {
                float2 f = __bfloat1622float2(*reinterpret_cast<__nv_bfloat162*>(&w4[j]));
                q[t * 8 + j * 2] = f.x; q[t * 8 + j * 2 + 1] = f.y;
            }
        }
        float w[NK];
        float mx = -1e30f;
#pragma unroll
        for (int k = 0; k < NK; k++) {
            const float* kp = Ks + k * 512 + doff;
            float d = 0.f;
#pragma unroll
            for (int j4 = 0; j4 < 8; j4++) {
                float4 kv = *(const float4*)(kp + j4 * 4);
                d += q[j4*4+0]*kv.x + q[j4*4+1]*kv.y + q[j4*4+2]*kv.z + q[j4*4+3]*kv.w;
            }
            d += __shfl_xor_sync(0xffffffffu, d, 1);
            float lg = d * 0.125f + kmf[k];
            w[k] = lg;
            mx = fmaxf(mx, lg);
        }
        float s = 0.f;
#pragma unroll
        for (int k = 0; k < NK; k++) { w[k] = __expf(w[k] - mx); s += w[k]; }
        const float inv = 1.f / s;

        float o[32];
#pragma unroll
        for (int j = 0; j < 32; j++) o[j] = 0.f;
#pragma unroll
        for (int k = 0; k < NK; k++) {
            const float wk = w[k];
            const float* vp = Vs + k * 512 + doff;
#pragma unroll
            for (int j4 = 0; j4 < 8; j4++) {
                float4 vv = *(const float4*)(vp + j4 * 4);
                o[j4*4+0] += wk * vv.x; o[j4*4+1] += wk * vv.y;
                o[j4*4+2] += wk * vv.z; o[j4*4+3] += wk * vv.w;
            }
        }
#pragma unroll
        for (int j = 0; j < 32; j++) o[j] *= inv;

        if (!ACC) {
            uint32_t pk[16];
#pragma unroll
            for (int i = 0; i < 16; i++) {
                __nv_bfloat162 hh = __floats2bfloat162_rn(o[2 * i], o[2 * i + 1]);
                pk[i] = *reinterpret_cast<uint32_t*>(&hh);
            }
            uint4* op = (uint4*)(OUT + (size_t)row * ldo + ooff + doff);
            op[0] = make_uint4(pk[0], pk[1], pk[2], pk[3]);
            op[1] = make_uint4(pk[4], pk[5], pk[6], pk[7]);
            op[2] = make_uint4(pk[8], pk[9], pk[10], pk[11]);
            op[3] = make_uint4(pk[12], pk[13], pk[14], pk[15]);
        } else {
#pragma unroll
            for (int st = 2; st < 32; st <<= 1)
#pragma unroll
                for (int j = 0; j < 32; j++) o[j] += __shfl_xor_sync(0xffffffffu, o[j], st);
            if (r == 0) {
#pragma unroll
                for (int j = 0; j < 32; j++) wacc[warp][doff + j] += o[j];
            }
        }
    }

    if (ACC) {
        __syncthreads();
        float* dst = PART + ((size_t)b * 16 + (blockIdx.x & 15)) * 512;
        for (int i = tid; i < 512; i += 256) {
            float s = 0.f;
#pragma unroll
            for (int w8 = 0; w8 < 8; w8++) s += wacc[w8][i];
            dst[i] = s;
        }
    }
}

// ===================================================================
// K/V head tables + folded bias rows (exact fp32)
// ===================================================================
__global__ void prep_rows(const float* __restrict__ ctab, const float* __restrict__ mtab,
                          const float* __restrict__ cWk, const float* __restrict__ cbk,
                          const float* __restrict__ cWv, const float* __restrict__ cbv,
                          const float* __restrict__ mWk, const float* __restrict__ mbk,
                          const float* __restrict__ mWv, const float* __restrict__ mbv,
                          const float* __restrict__ b_lin,
                          const float* __restrict__ cWq, const float* __restrict__ cbq,
                          const float* __restrict__ mWq, const float* __restrict__ mbq,
                          const float* __restrict__ cbo, const float* __restrict__ mbo)
{
    const int id = blockIdx.x;
    const float* arow; const float* W; const float* bb; float* out;
    if      (id < 19)  { arow = ctab + id * 512;        W = cWk; bb = cbk; out = g_Kc + id * 512; }
    else if (id < 38)  { arow = ctab + (id - 19) * 512; W = cWv; bb = cbv; out = g_Vc + (id - 19) * 512; }
    else if (id < 48)  { arow = mtab + (id - 38) * 512; W = mWk; bb = mbk; out = g_Km + (id - 38) * 512; }
    else if (id < 58)  { arow = mtab + (id - 48) * 512; W = mWv; bb = mbv; out = g_Vm + (id - 48) * 512; }
    else if (id == 58) { arow = b_lin; W = cWq; bb = cbq; out = g_bf1; }
    else if (id == 59) { arow = b_lin; W = mWq; bb = mbq; out = g_bf1 + 512; }
    else if (id == 60) { arow = cbo;   W = cWq; bb = cbq; out = g_bf2c; }
    else               { arow = mbo;   W = mWq; bb = mbq; out = g_bf2m; }

    __shared__ float sA[512];
    const int c = threadIdx.x;
    sA[c] = arow[c];
    __syncthreads();
    float acc = bb[c];
    for (int k = 0; k < 512; k++) acc += sA[k] * W[k * 512 + c];
    out[c] = acc;
}

__global__ void pmsum_kernel(const int* __restrict__ em, const int* __restrict__ pmask)
{
    __shared__ int sred[8];
    const int b = blockIdx.x, t = threadIdx.x;
    int cnt = 0;
    for (int s = t; s < SEQ; s += 256) cnt += em[b * SEQ + s] * pmask[b * SEQ + s];
#pragma unroll
    for (int st = 16; st; st >>= 1) cnt += __shfl_xor_sync(0xffffffffu, cnt, st);
    if ((t & 31) == 0) sred[t >> 5] = cnt;
    __syncthreads();
    if (t == 0) { int tot = 0; for (int w = 0; w < 8; w++) tot += sred[w]; g_pmsum[b] = (float)tot; }
}

__global__ void final_kernel(const float* __restrict__ cWo, const float* __restrict__ cbo,
                             const float* __restrict__ mWo, const float* __restrict__ mbo,
                             float* __restrict__ out)
{
    __shared__ float sc[512], sm2[512];
    const int b = blockIdx.x, c = threadIdx.x;
    float a0 = 0.f, a1 = 0.f;
#pragma unroll
    for (int p = 0; p < 16; p++) { a0 += g_part[0][b][p][c]; a1 += g_part[1][b][p][c]; }
    sc[c] = a0; sm2[c] = a1;
    __syncthreads();
    float oc = 0.f, om = 0.f;
    for (int k = 0; k < 512; k++) {
        oc += sc[k]  * cWo[k * 512 + c];
        om += sm2[k] * mWo[k * 512 + c];
    }
    const float invp = 1.f / g_pmsum[b];
    oc = (oc + 2048.f * cbo[c]) * invp;
    om = (om + 2048.f * mbo[c]) * invp;
    out[b * 512 + c] = oc;
    out[BATCH * 512 + b * 512 + c] = oc - om;
}

// ===================================================================
extern "C" void kernel_launch(void* const* d_in, const int* in_sizes, int n_in,
                              void* d_out, int out_size)
{
    const float* emb   = (const float*)d_in[0];
    const int*   emask = (const int*)d_in[1];
    const int*   pmask = (const int*)d_in[2];
    // d_in[3] (frame_mask) cancels in softmax — unused
    const int*   cmask = (const int*)d_in[4];
    const int*   mmask = (const int*)d_in[5];
    const float* W_lin = (const float*)d_in[6];
    const float* b_lin = (const float*)d_in[7];
    const float* ctab  = (const float*)d_in[8];
    const float* mtab  = (const float*)d_in[9];
    const float* cWq = (const float*)d_in[10]; const float* cbq = (const float*)d_in[11];
    const float* cWk = (const float*)d_in[12]; const float* cbk = (const float*)d_in[13];
    const float* cWv = (const float*)d_in[14]; const float* cbv = (const float*)d_in[15];
    const float* cWo = (const float*)d_in[16]; const float* cbo = (const float*)d_in[17];
    const float* mWq = (const float*)d_in[18]; const float* mbq = (const float*)d_in[19];
    const float* mWk = (const float*)d_in[20]; const float* mbk = (const float*)d_in[21];
    const float* mWv = (const float*)d_in[22]; const float* mbv = (const float*)d_in[23];
    const float* mWo = (const float*)d_in[24]; const float* mbo = (const float*)d_in[25];
    float* out = (float*)d_out;

    __nv_bfloat16 *pE, *pQ1, *pAV1, *pWf1T, *pWf2cT, *pWf2mT;
    float *pbf1, *pbf2c, *pbf2m, *pKc, *pVc, *pKm, *pVm, *pPart;
    cudaGetSymbolAddress((void**)&pE,     g_emb16);
    cudaGetSymbolAddress((void**)&pQ1,    g_Q1);
    cudaGetSymbolAddress((void**)&pAV1,   g_AV1);
    cudaGetSymbolAddress((void**)&pWf1T,  g_Wf1T);
    cudaGetSymbolAddress((void**)&pWf2cT, g_Wf2cT);
    cudaGetSymbolAddress((void**)&pWf2mT, g_Wf2mT);
    cudaGetSymbolAddress((void**)&pbf1,   g_bf1);
    cudaGetSymbolAddress((void**)&pbf2c,  g_bf2c);
    cudaGetSymbolAddress((void**)&pbf2m,  g_bf2m);
    cudaGetSymbolAddress((void**)&pKc,    g_Kc);
    cudaGetSymbolAddress((void**)&pVc,    g_Vc);
    cudaGetSymbolAddress((void**)&pKm,    g_Km);
    cudaGetSymbolAddress((void**)&pVm,    g_Vm);
    cudaGetSymbolAddress((void**)&pPart,  g_part);

    const int smemC = NCULT  * 1024 * 4;
    const int smemM = NMORAL * 1024 * 4;
    cudaFuncSetAttribute(attn_kernel<NCULT,  false>, cudaFuncAttributeMaxDynamicSharedMemorySize, smemC);
    cudaFuncSetAttribute(attn_kernel<NCULT,  true >, cudaFuncAttributeMaxDynamicSharedMemorySize, smemC);
    cudaFuncSetAttribute(attn_kernel<NMORAL, false>, cudaFuncAttributeMaxDynamicSharedMemorySize, smemM);
    cudaFuncSetAttribute(attn_kernel<NMORAL, true >, cudaFuncAttributeMaxDynamicSharedMemorySize, smemM);

    // conversion + small preps
    conv_bf16_kernel<<<2048, 256>>>((const float4*)emb, (uint4*)pE, NROWS * 1024 / 8);
    prep_rows<<<62, 512>>>(ctab, mtab, cWk, cbk, cWv, cbv, mWk, mbk, mWv, mbv,
                           b_lin, cWq, cbq, mWq, mbq, cbo, mbo);
    pmsum_kernel<<<BATCH, 256>>>(emask, pmask);
    fold_gemm<<<dim3(4, 8, 4), 256>>>(W_lin, cWq, mWq, cWo, mWo, pWf1T, pWf2cT, pWf2mT);

    // G1: Q1(c|m) = emb16 @ Wf1T^T + bf1   [65536x1024] x [1024x1024]
    gemm_bf16<<<dim3(1024 / GBN, NROWS / GBM), 256>>>(pE, 1024, pWf1T, 1024, pQ1, 1024, pbf1, 32);

    // attention layer 1 -> AV1 (bf16)
    attn_kernel<NCULT,  false><<<512, 256, smemC>>>(pQ1, 1024, 0,   pKc, pVc, cmask, pAV1, 1024, 0,   nullptr);
    attn_kernel<NMORAL, false><<<512, 256, smemM>>>(pQ1, 1024, 512, pKm, pVm, mmask, pAV1, 1024, 512, nullptr);

    // G2: Q2 = AV1 @ Wf2T^T + fold-bias (written back into g_Q1 columns)
    gemm_bf16<<<dim3(512 / GBN, NROWS / GBM), 256>>>(pAV1,       1024, pWf2cT, 512, pQ1,       1024, pbf2c, 16);
    gemm_bf16<<<dim3(512 / GBN, NROWS / GBM), 256>>>(pAV1 + 512, 1024, pWf2mT, 512, pQ1 + 512, 1024, pbf2m, 16);

    // attention layer 2 with fused sequence-sum -> g_part
    attn_kernel<NCULT,  true><<<512, 256, smemC>>>(pQ1, 1024, 0,   pKc, pVc, cmask, nullptr, 0, 0, pPart);
    attn_kernel<NMORAL, true><<<512, 256, smemM>>>(pQ1, 1024, 512, pKm, pVm, mmask, nullptr, 0, 0,
                                                   pPart + (size_t)BATCH * 16 * 512);

    final_kernel<<<BATCH, 512>>>(cWo, cbo, mWo, mbo, out);
}

// round 4
// speedup vs baseline: 1.5713x; 1.5319x over previous
#include <cuda_runtime.h>
#include <cuda_bf16.h>
#include <cstdint>

// ---------------- problem constants ----------------
#define BATCH 32
#define SEQ   2048
#define NHEAD 8
#define NCULT 19
#define NMORAL 10
#define NROWS (BATCH*SEQ)   // 65536

// ---------------- scratch (device globals; no allocation allowed) ----------------
__device__ __nv_bfloat16 g_emb16[(size_t)NROWS*1024];  // 128MB bf16 embeddings
__device__ __nv_bfloat16 g_Q1[(size_t)NROWS*1024];     // 128MB Q1c|Q1m, reused for Q2
__device__ __nv_bfloat16 g_AV1[(size_t)NROWS*1024];    // 128MB AV1c|AV1m
__device__ __nv_bfloat16 g_Wf1T[1024*1024];            // [n][k] = (W_lin@Wq)[k][n], c|m stacked in n
__device__ __nv_bfloat16 g_Wf2cT[512*512];             // [n][k] = (c_Wo@c_Wq)[k][n]
__device__ __nv_bfloat16 g_Wf2mT[512*512];
__device__ float g_bf1[1024];
__device__ float g_bf2c[512];
__device__ float g_bf2m[512];
__device__ float g_Kc[NCULT*512],  g_Vc[NCULT*512];
__device__ float g_Km[NMORAL*512], g_Vm[NMORAL*512];
__device__ float g_pmsum[BATCH];
__device__ float g_part[2][BATCH][16][512];

__device__ __forceinline__ uint32_t smem_u32(const void* p) {
    return (uint32_t)__cvta_generic_to_shared(p);
}
__device__ __forceinline__ void cp_async16(uint32_t dst, const void* src) {
    asm volatile("cp.async.cg.shared.global [%0], [%1], 16;" :: "r"(dst), "l"(src));
}
__device__ __forceinline__ uint32_t sw128(uint32_t b) { return b ^ ((b >> 3) & 0x70u); }

// ===================================================================
// bf16 mma.sync GEMM: C[M,N](bf16) = A[M,K](bf16) @ B^T + fp32 bias
//   B stored [N,K] bf16 (K-major). Tile 128x128, BK=32, 3 stages.
//   256 threads, 8 warps (2x4), warp tile 64x32. ldmatrix-fed fragments.
// ===================================================================
#define GBM 128
#define GBN 128
#define GBK 32
#define STG 3
#define STAGE_B 16384   // A 8KB + B 8KB

__global__ __launch_bounds__(256, 2)
void gemm_bf16(const __nv_bfloat16* __restrict__ A, int lda,
               const __nv_bfloat16* __restrict__ B, int ldb,
               __nv_bfloat16* __restrict__ C, int ldc,
               const float* __restrict__ bias, int KT)
{
    __shared__ __align__(1024) char sm[STG * STAGE_B];
    const uint32_t sbase = smem_u32(sm);

    const int tid  = threadIdx.x;
    const int warp = tid >> 5, lane = tid & 31;
    const int wm = warp >> 2;        // 0..1 -> m offset *64
    const int wn = warp & 3;         // 0..3 -> n offset *32
    const int m0 = blockIdx.y * GBM;
    const int n0 = blockIdx.x * GBN;

    float acc[4][4][4];
#pragma unroll
    for (int i = 0; i < 4; i++)
#pragma unroll
        for (int j = 0; j < 4; j++) {
            acc[i][j][0] = 0.f; acc[i][j][1] = 0.f; acc[i][j][2] = 0.f; acc[i][j][3] = 0.f;
        }

    // cp.async: 512 chunks of 16B per operand per stage, 2 per thread
    auto load_stage = [&](int s, int kt) {
        const uint32_t ab = sbase + s * STAGE_B;
        const uint32_t bb = ab + 8192;
        const __nv_bfloat16* Ag = A + kt * GBK;
        const __nv_bfloat16* Bg = B + kt * GBK;
#pragma unroll
        for (int t = 0; t < 2; t++) {
            int id  = tid + t * 256;
            int row = id >> 2, c = id & 3;
            uint32_t byte = row * 64 + c * 16;
            cp_async16(ab + sw128(byte), Ag + (size_t)(m0 + row) * lda + c * 8);
            cp_async16(bb + sw128(byte), Bg + (size_t)(n0 + row) * ldb + c * 8);
        }
    };

    load_stage(0, 0);
    asm volatile("cp.async.commit_group;");
    load_stage(1, 1);
    asm volatile("cp.async.commit_group;");

    // per-lane ldmatrix row/col components
    const int a_row = lane & 15;                 // row within m16
    const int a_k8  = (lane >> 4) << 3;          // k half select
    const int b_row = (lane & 7) | ((lane >> 4) << 3);   // row within n16
    const int b_k8  = ((lane >> 3) & 1) << 3;    // k half select

    for (int kt = 0; kt < KT; kt++) {
        const int buf = kt % STG;
        asm volatile("cp.async.wait_group 1;");
        __syncthreads();
        if (kt + 2 < KT) load_stage((kt + 2) % STG, kt + 2);
        asm volatile("cp.async.commit_group;");

        const uint32_t aS = sbase + buf * STAGE_B;
        const uint32_t bS = aS + 8192;

#pragma unroll
        for (int kk = 0; kk < 2; kk++) {          // two k16 steps
            uint32_t a[4][4], b[2][4];
#pragma unroll
            for (int mt = 0; mt < 4; mt++) {
                uint32_t byte = (uint32_t)(wm * 64 + mt * 16 + a_row) * 64
                              + (uint32_t)(kk * 16 + a_k8) * 2;
                uint32_t ad = aS + sw128(byte);
                asm volatile(
                    "ldmatrix.sync.aligned.m8n8.x4.shared.b16 {%0,%1,%2,%3}, [%4];"
                    : "=r"(a[mt][0]), "=r"(a[mt][1]), "=r"(a[mt][2]), "=r"(a[mt][3])
                    : "r"(ad));
            }
#pragma unroll
            for (int np = 0; np < 2; np++) {
                uint32_t byte = (uint32_t)(wn * 32 + np * 16 + b_row) * 64
                              + (uint32_t)(kk * 16 + b_k8) * 2;
                uint32_t bd = bS + sw128(byte);
                asm volatile(
                    "ldmatrix.sync.aligned.m8n8.x4.shared.b16 {%0,%1,%2,%3}, [%4];"
                    : "=r"(b[np][0]), "=r"(b[np][1]), "=r"(b[np][2]), "=r"(b[np][3])
                    : "r"(bd));
            }
#pragma unroll
            for (int mt = 0; mt < 4; mt++)
#pragma unroll
                for (int nt = 0; nt < 4; nt++) {
                    const uint32_t b0 = b[nt >> 1][(nt & 1) * 2];
                    const uint32_t b1 = b[nt >> 1][(nt & 1) * 2 + 1];
                    asm volatile(
                        "mma.sync.aligned.m16n8k16.row.col.f32.bf16.bf16.f32 "
                        "{%0,%1,%2,%3}, {%4,%5,%6,%7}, {%8,%9}, {%0,%1,%2,%3};"
                        : "+f"(acc[mt][nt][0]), "+f"(acc[mt][nt][1]),
                          "+f"(acc[mt][nt][2]), "+f"(acc[mt][nt][3])
                        : "r"(a[mt][0]), "r"(a[mt][1]), "r"(a[mt][2]), "r"(a[mt][3]),
                          "r"(b0), "r"(b1));
                }
        }
        __syncthreads();
    }

    // epilogue: bias + bf16 store
#pragma unroll
    for (int mt = 0; mt < 4; mt++) {
        const int r0 = m0 + wm * 64 + mt * 16 + (lane >> 2);
#pragma unroll
        for (int nt = 0; nt < 4; nt++) {
            const int gc = n0 + wn * 32 + nt * 8 + (lane & 3) * 2;
            float bb0 = 0.f, bb1 = 0.f;
            if (bias) { bb0 = bias[gc]; bb1 = bias[gc + 1]; }
            __nv_bfloat162 h0 = __floats2bfloat162_rn(acc[mt][nt][0] + bb0, acc[mt][nt][1] + bb1);
            __nv_bfloat162 h1 = __floats2bfloat162_rn(acc[mt][nt][2] + bb0, acc[mt][nt][3] + bb1);
            *reinterpret_cast<__nv_bfloat162*>(C + (size_t)r0 * ldc + gc)       = h0;
            *reinterpret_cast<__nv_bfloat162*>(C + (size_t)(r0 + 8) * ldc + gc) = h1;
        }
    }
}

// ===================================================================
// fold GEMMs (tf32 mma.sync, exact-ish): all four weight folds in ONE launch.
// Writes bf16 TRANSPOSED output: CT[n][k] = (A@B)[k][n].
// ===================================================================
#define BM 128
#define BN 128
#define BKT 16
#define BKP 20
#define BNP 136

__global__ __launch_bounds__(256, 2)
void fold_gemm(const float* __restrict__ W_lin,
               const float* __restrict__ cWq, const float* __restrict__ mWq,
               const float* __restrict__ cWo, const float* __restrict__ mWo,
               __nv_bfloat16* __restrict__ Wf1T,
               __nv_bfloat16* __restrict__ Wf2cT,
               __nv_bfloat16* __restrict__ Wf2mT)
{
    const int z = blockIdx.z;
    const float* A; const float* B; __nv_bfloat16* CT; int ldt, Mrows;
    if (z == 0)      { A = W_lin; B = cWq; CT = Wf1T;              ldt = 1024; Mrows = 1024; }
    else if (z == 1) { A = W_lin; B = mWq; CT = Wf1T + 512 * 1024; ldt = 1024; Mrows = 1024; }
    else if (z == 2) { A = cWo;   B = cWq; CT = Wf2cT;             ldt = 512;  Mrows = 512; }
    else             { A = mWo;   B = mWq; CT = Wf2mT;             ldt = 512;  Mrows = 512; }
    if (blockIdx.y * BM >= Mrows) return;

    __shared__ float As[2][BM][BKP];
    __shared__ float Bs[2][BKT][BNP];

    const int tid  = threadIdx.x;
    const int warp = tid >> 5;
    const int lane = tid & 31;
    const int wm = warp >> 2;
    const int wn = warp & 3;
    const int m0 = blockIdx.y * BM;
    const int n0 = blockIdx.x * BN;
    const int lda = 512, ldb = 512, Ktiles = 32;

    float acc[4][4][4];
#pragma unroll
    for (int i = 0; i < 4; i++)
#pragma unroll
        for (int j = 0; j < 4; j++)
#pragma unroll
            for (int r = 0; r < 4; r++) acc[i][j][r] = 0.f;

    auto loadA = [&](int stage, int kt) {
        const int k0 = kt * BKT;
#pragma unroll
        for (int t = 0; t < 2; t++) {
            int i = tid + t * 256;
            int row = i >> 2, k4 = i & 3;
            cp_async16(smem_u32(&As[stage][row][k4 * 4]),
                       A + (size_t)(m0 + row) * lda + k0 + k4 * 4);
        }
    };
    auto loadB = [&](int stage, int kt) {
        const int k0 = kt * BKT;
#pragma unroll
        for (int t = 0; t < 2; t++) {
            int i = tid + t * 256;
            int row = i >> 5, n4 = i & 31;
            cp_async16(smem_u32(&Bs[stage][row][n4 * 4]),
                       B + (size_t)(k0 + row) * ldb + n0 + n4 * 4);
        }
    };

    loadA(0, 0); loadB(0, 0);
    asm volatile("cp.async.commit_group;\n");

    for (int kt = 0; kt < Ktiles; kt++) {
        const int cur = kt & 1;
        if (kt + 1 < Ktiles) {
            loadA(cur ^ 1, kt + 1); loadB(cur ^ 1, kt + 1);
            asm volatile("cp.async.commit_group;\n");
            asm volatile("cp.async.wait_group 1;\n");
        } else {
            asm volatile("cp.async.wait_group 0;\n");
        }
        __syncthreads();

#pragma unroll
        for (int ks = 0; ks < 2; ks++) {
            uint32_t a[4][4], b[4][2];
            const int kc = ks * 8 + (lane & 3);
            const int rr = wm * 64 + (lane >> 2);
#pragma unroll
            for (int mt = 0; mt < 4; mt++) {
                a[mt][0] = __float_as_uint(As[cur][rr + mt * 16][kc]);
                a[mt][1] = __float_as_uint(As[cur][rr + mt * 16 + 8][kc]);
                a[mt][2] = __float_as_uint(As[cur][rr + mt * 16][kc + 4]);
                a[mt][3] = __float_as_uint(As[cur][rr + mt * 16 + 8][kc + 4]);
            }
            const int cc = wn * 32 + (lane >> 2);
#pragma unroll
            for (int nt = 0; nt < 4; nt++) {
                b[nt][0] = __float_as_uint(Bs[cur][ks * 8 + (lane & 3)][cc + nt * 8]);
                b[nt][1] = __float_as_uint(Bs[cur][ks * 8 + (lane & 3) + 4][cc + nt * 8]);
            }
#pragma unroll
            for (int mt = 0; mt < 4; mt++)
#pragma unroll
                for (int nt = 0; nt < 4; nt++) {
                    asm volatile(
                        "mma.sync.aligned.m16n8k8.row.col.f32.tf32.tf32.f32 "
                        "{%0,%1,%2,%3}, {%4,%5,%6,%7}, {%8,%9}, {%0,%1,%2,%3};\n"
                        : "+f"(acc[mt][nt][0]), "+f"(acc[mt][nt][1]),
                          "+f"(acc[mt][nt][2]), "+f"(acc[mt][nt][3])
                        : "r"(a[mt][0]), "r"(a[mt][1]), "r"(a[mt][2]), "r"(a[mt][3]),
                          "r"(b[nt][0]), "r"(b[nt][1]));
                }
        }
        __syncthreads();
    }

    // epilogue: transposed bf16 store CT[n][k]
#pragma unroll
    for (int mt = 0; mt < 4; mt++) {
        const int grow = m0 + wm * 64 + mt * 16 + (lane >> 2);
#pragma unroll
        for (int nt = 0; nt < 4; nt++) {
            const int gcol = n0 + wn * 32 + nt * 8 + (lane & 3) * 2;
            CT[(size_t)gcol * ldt + grow]           = __float2bfloat16(acc[mt][nt][0]);
            CT[(size_t)(gcol + 1) * ldt + grow]     = __float2bfloat16(acc[mt][nt][1]);
            CT[(size_t)gcol * ldt + grow + 8]       = __float2bfloat16(acc[mt][nt][2]);
            CT[(size_t)(gcol + 1) * ldt + grow + 8] = __float2bfloat16(acc[mt][nt][3]);
        }
    }
}

// ===================================================================
// fp32 -> bf16 conversion (embeddings)
// ===================================================================
__global__ void conv_bf16_kernel(const float4* __restrict__ in, uint4* __restrict__ out, int n16)
{
    int i = blockIdx.x * blockDim.x + threadIdx.x;
    const int stride = gridDim.x * blockDim.x;
    for (; i < n16; i += stride) {
        float4 a = in[2 * i], b = in[2 * i + 1];
        __nv_bfloat162 h0 = __floats2bfloat162_rn(a.x, a.y);
        __nv_bfloat162 h1 = __floats2bfloat162_rn(a.z, a.w);
        __nv_bfloat162 h2 = __floats2bfloat162_rn(b.x, b.y);
        __nv_bfloat162 h3 = __floats2bfloat162_rn(b.z, b.w);
        out[i] = make_uint4(*reinterpret_cast<uint32_t*>(&h0), *reinterpret_cast<uint32_t*>(&h1),
                            *reinterpret_cast<uint32_t*>(&h2), *reinterpret_cast<uint32_t*>(&h3));
    }
}

// ===================================================================
// Attention (bf16 Q, fp32 K/V in smem).
// ===================================================================
template<int NK, bool ACC>
__global__ void attn_kernel(const __nv_bfloat16* __restrict__ Q, int ldq, int qoff,
                            const float* __restrict__ Kh, const float* __restrict__ Vh,
                            const int* __restrict__ kmask,
                            __nv_bfloat16* __restrict__ OUT, int ldo, int ooff,
                            float* __restrict__ PART)
{
    extern __shared__ float sh[];
    float* Ks = sh;
    float* Vs = sh + NK * 512;
    __shared__ float kmf[32];
    __shared__ float wacc[ACC ? 8 : 1][ACC ? 512 : 1];

    const int tid  = threadIdx.x;
    const int row0 = blockIdx.x * 128;
    const int b    = row0 >> 11;

    for (int i = tid; i < NK * 512; i += 256) { Ks[i] = Kh[i]; Vs[i] = Vh[i]; }
    if (tid < NK) kmf[tid] = (float)kmask[b * NK + tid];
    if (ACC) for (int i = tid; i < 8 * 512; i += 256) ((float*)wacc)[i] = 0.f;
    __syncthreads();

    const int warp = tid >> 5, lane = tid & 31;
    const int r = lane >> 1, half = lane & 1;
    const int row = row0 + warp * 16 + r;
    const __nv_bfloat16* qrow = Q + (size_t)row * ldq + qoff;

#pragma unroll 1
    for (int h = 0; h < NHEAD; h++) {
        const int doff = h * 64 + half * 32;
        float q[32];
        const uint4* q4 = reinterpret_cast<const uint4*>(qrow + doff);
#pragma unroll
        for (int t = 0; t < 4; t++) {
            uint4 u = q4[t];
            uint32_t w4[4] = {u.x, u.y, u.z, u.w};
#pragma unroll
            for (int j = 0; j < 4; j++) {
                float2 f = __bfloat1622float2(*reinterpret_cast<__nv_bfloat162*>(&w4[j]));
                q[t * 8 + j * 2] = f.x; q[t * 8 + j * 2 + 1] = f.y;
            }
        }
        float w[NK];
        float mx = -1e30f;
#pragma unroll
        for (int k = 0; k < NK; k++) {
            const float* kp = Ks + k * 512 + doff;
            float d = 0.f;
#pragma unroll
            for (int j4 = 0; j4 < 8; j4++) {
                float4 kv = *(const float4*)(kp + j4 * 4);
                d += q[j4*4+0]*kv.x + q[j4*4+1]*kv.y + q[j4*4+2]*kv.z + q[j4*4+3]*kv.w;
            }
            d += __shfl_xor_sync(0xffffffffu, d, 1);
            float lg = d * 0.125f + kmf[k];
            w[k] = lg;
            mx = fmaxf(mx, lg);
        }
        float s = 0.f;
#pragma unroll
        for (int k = 0; k < NK; k++) { w[k] = __expf(w[k] - mx); s += w[k]; }
        const float inv = 1.f / s;

        float o[32];
#pragma unroll
        for (int j = 0; j < 32; j++) o[j] = 0.f;
#pragma unroll
        for (int k = 0; k < NK; k++) {
            const float wk = w[k];
            const float* vp = Vs + k * 512 + doff;
#pragma unroll
            for (int j4 = 0; j4 < 8; j4++) {
                float4 vv = *(const float4*)(vp + j4 * 4);
                o[j4*4+0] += wk * vv.x; o[j4*4+1] += wk * vv.y;
                o[j4*4+2] += wk * vv.z; o[j4*4+3] += wk * vv.w;
            }
        }
#pragma unroll
        for (int j = 0; j < 32; j++) o[j] *= inv;

        if (!ACC) {
            uint32_t pk[16];
#pragma unroll
            for (int i = 0; i < 16; i++) {
                __nv_bfloat162 hh = __floats2bfloat162_rn(o[2 * i], o[2 * i + 1]);
                pk[i] = *reinterpret_cast<uint32_t*>(&hh);
            }
            uint4* op = (uint4*)(OUT + (size_t)row * ldo + ooff + doff);
            op[0] = make_uint4(pk[0], pk[1], pk[2], pk[3]);
            op[1] = make_uint4(pk[4], pk[5], pk[6], pk[7]);
            op[2] = make_uint4(pk[8], pk[9], pk[10], pk[11]);
            op[3] = make_uint4(pk[12], pk[13], pk[14], pk[15]);
        } else {
#pragma unroll
            for (int st = 2; st < 32; st <<= 1)
#pragma unroll
                for (int j = 0; j < 32; j++) o[j] += __shfl_xor_sync(0xffffffffu, o[j], st);
            if (r == 0) {
#pragma unroll
                for (int j = 0; j < 32; j++) wacc[warp][doff + j] += o[j];
            }
        }
    }

    if (ACC) {
        __syncthreads();
        float* dst = PART + ((size_t)b * 16 + (blockIdx.x & 15)) * 512;
        for (int i = tid; i < 512; i += 256) {
            float s = 0.f;
#pragma unroll
            for (int w8 = 0; w8 < 8; w8++) s += wacc[w8][i];
            dst[i] = s;
        }
    }
}

// ===================================================================
// K/V head tables + folded bias rows (exact fp32)
// ===================================================================
__global__ void prep_rows(const float* __restrict__ ctab, const float* __restrict__ mtab,
                          const float* __restrict__ cWk, const float* __restrict__ cbk,
                          const float* __restrict__ cWv, const float* __restrict__ cbv,
                          const float* __restrict__ mWk, const float* __restrict__ mbk,
                          const float* __restrict__ mWv, const float* __restrict__ mbv,
                          const float* __restrict__ b_lin,
                          const float* __restrict__ cWq, const float* __restrict__ cbq,
                          const float* __restrict__ mWq, const float* __restrict__ mbq,
                          const float* __restrict__ cbo, const float* __restrict__ mbo)
{
    const int id = blockIdx.x;
    const float* arow; const float* W; const float* bb; float* out;
    if      (id < 19)  { arow = ctab + id * 512;        W = cWk; bb = cbk; out = g_Kc + id * 512; }
    else if (id < 38)  { arow = ctab + (id - 19) * 512; W = cWv; bb = cbv; out = g_Vc + (id - 19) * 512; }
    else if (id < 48)  { arow = mtab + (id - 38) * 512; W = mWk; bb = mbk; out = g_Km + (id - 38) * 512; }
    else if (id < 58)  { arow = mtab + (id - 48) * 512; W = mWv; bb = mbv; out = g_Vm + (id - 48) * 512; }
    else if (id == 58) { arow = b_lin; W = cWq; bb = cbq; out = g_bf1; }
    else if (id == 59) { arow = b_lin; W = mWq; bb = mbq; out = g_bf1 + 512; }
    else if (id == 60) { arow = cbo;   W = cWq; bb = cbq; out = g_bf2c; }
    else               { arow = mbo;   W = mWq; bb = mbq; out = g_bf2m; }

    __shared__ float sA[512];
    const int c = threadIdx.x;
    sA[c] = arow[c];
    __syncthreads();
    float acc = bb[c];
    for (int k = 0; k < 512; k++) acc += sA[k] * W[k * 512 + c];
    out[c] = acc;
}

__global__ void pmsum_kernel(const int* __restrict__ em, const int* __restrict__ pmask)
{
    __shared__ int sred[8];
    const int b = blockIdx.x, t = threadIdx.x;
    int cnt = 0;
    for (int s = t; s < SEQ; s += 256) cnt += em[b * SEQ + s] * pmask[b * SEQ + s];
#pragma unroll
    for (int st = 16; st; st >>= 1) cnt += __shfl_xor_sync(0xffffffffu, cnt, st);
    if ((t & 31) == 0) sred[t >> 5] = cnt;
    __syncthreads();
    if (t == 0) { int tot = 0; for (int w = 0; w < 8; w++) tot += sred[w]; g_pmsum[b] = (float)tot; }
}

__global__ void final_kernel(const float* __restrict__ cWo, const float* __restrict__ cbo,
                             const float* __restrict__ mWo, const float* __restrict__ mbo,
                             float* __restrict__ out)
{
    __shared__ float sc[512], sm2[512];
    const int b = blockIdx.x, c = threadIdx.x;
    float a0 = 0.f, a1 = 0.f;
#pragma unroll
    for (int p = 0; p < 16; p++) { a0 += g_part[0][b][p][c]; a1 += g_part[1][b][p][c]; }
    sc[c] = a0; sm2[c] = a1;
    __syncthreads();
    float oc = 0.f, om = 0.f;
    for (int k = 0; k < 512; k++) {
        oc += sc[k]  * cWo[k * 512 + c];
        om += sm2[k] * mWo[k * 512 + c];
    }
    const float invp = 1.f / g_pmsum[b];
    oc = (oc + 2048.f * cbo[c]) * invp;
    om = (om + 2048.f * mbo[c]) * invp;
    out[b * 512 + c] = oc;
    out[BATCH * 512 + b * 512 + c] = oc - om;
}

// ===================================================================
extern "C" void kernel_launch(void* const* d_in, const int* in_sizes, int n_in,
                              void* d_out, int out_size)
{
    const float* emb   = (const float*)d_in[0];
    const int*   emask = (const int*)d_in[1];
    const int*   pmask = (const int*)d_in[2];
    // d_in[3] (frame_mask) cancels in softmax — unused
    const int*   cmask = (const int*)d_in[4];
    const int*   mmask = (const int*)d_in[5];
    const float* W_lin = (const float*)d_in[6];
    const float* b_lin = (const float*)d_in[7];
    const float* ctab  = (const float*)d_in[8];
    const float* mtab  = (const float*)d_in[9];
    const float* cWq = (const float*)d_in[10]; const float* cbq = (const float*)d_in[11];
    const float* cWk = (const float*)d_in[12]; const float* cbk = (const float*)d_in[13];
    const float* cWv = (const float*)d_in[14]; const float* cbv = (const float*)d_in[15];
    const float* cWo = (const float*)d_in[16]; const float* cbo = (const float*)d_in[17];
    const float* mWq = (const float*)d_in[18]; const float* mbq = (const float*)d_in[19];
    const float* mWk = (const float*)d_in[20]; const float* mbk = (const float*)d_in[21];
    const float* mWv = (const float*)d_in[22]; const float* mbv = (const float*)d_in[23];
    const float* mWo = (const float*)d_in[24]; const float* mbo = (const float*)d_in[25];
    float* out = (float*)d_out;

    __nv_bfloat16 *pE, *pQ1, *pAV1, *pWf1T, *pWf2cT, *pWf2mT;
    float *pbf1, *pbf2c, *pbf2m, *pKc, *pVc, *pKm, *pVm, *pPart;
    cudaGetSymbolAddress((void**)&pE,     g_emb16);
    cudaGetSymbolAddress((void**)&pQ1,    g_Q1);
    cudaGetSymbolAddress((void**)&pAV1,   g_AV1);
    cudaGetSymbolAddress((void**)&pWf1T,  g_Wf1T);
    cudaGetSymbolAddress((void**)&pWf2cT, g_Wf2cT);
    cudaGetSymbolAddress((void**)&pWf2mT, g_Wf2mT);
    cudaGetSymbolAddress((void**)&pbf1,   g_bf1);
    cudaGetSymbolAddress((void**)&pbf2c,  g_bf2c);
    cudaGetSymbolAddress((void**)&pbf2m,  g_bf2m);
    cudaGetSymbolAddress((void**)&pKc,    g_Kc);
    cudaGetSymbolAddress((void**)&pVc,    g_Vc);
    cudaGetSymbolAddress((void**)&pKm,    g_Km);
    cudaGetSymbolAddress((void**)&pVm,    g_Vm);
    cudaGetSymbolAddress((void**)&pPart,  g_part);

    const int smemC = NCULT  * 1024 * 4;
    const int smemM = NMORAL * 1024 * 4;
    cudaFuncSetAttribute(attn_kernel<NCULT,  false>, cudaFuncAttributeMaxDynamicSharedMemorySize, smemC);
    cudaFuncSetAttribute(attn_kernel<NCULT,  true >, cudaFuncAttributeMaxDynamicSharedMemorySize, smemC);
    cudaFuncSetAttribute(attn_kernel<NMORAL, false>, cudaFuncAttributeMaxDynamicSharedMemorySize, smemM);
    cudaFuncSetAttribute(attn_kernel<NMORAL, true >, cudaFuncAttributeMaxDynamicSharedMemorySize, smemM);

    // conversion + small preps
    conv_bf16_kernel<<<2048, 256>>>((const float4*)emb, (uint4*)pE, NROWS * 1024 / 8);
    prep_rows<<<62, 512>>>(ctab, mtab, cWk, cbk, cWv, cbv, mWk, mbk, mWv, mbv,
                           b_lin, cWq, cbq, mWq, mbq, cbo, mbo);
    pmsum_kernel<<<BATCH, 256>>>(emask, pmask);
    fold_gemm<<<dim3(4, 8, 4), 256>>>(W_lin, cWq, mWq, cWo, mWo, pWf1T, pWf2cT, pWf2mT);

    // G1: Q1(c|m) = emb16 @ Wf1T^T + bf1   [65536x1024] x [1024x1024]
    gemm_bf16<<<dim3(1024 / GBN, NROWS / GBM), 256>>>(pE, 1024, pWf1T, 1024, pQ1, 1024, pbf1, 32);

    // attention layer 1 -> AV1 (bf16)
    attn_kernel<NCULT,  false><<<512, 256, smemC>>>(pQ1, 1024, 0,   pKc, pVc, cmask, pAV1, 1024, 0,   nullptr);
    attn_kernel<NMORAL, false><<<512, 256, smemM>>>(pQ1, 1024, 512, pKm, pVm, mmask, pAV1, 1024, 512, nullptr);

    // G2: Q2 = AV1 @ Wf2T^T + fold-bias (written back into g_Q1 columns)
    gemm_bf16<<<dim3(512 / GBN, NROWS / GBM), 256>>>(pAV1,       1024, pWf2cT, 512, pQ1,       1024, pbf2c, 16);
    gemm_bf16<<<dim3(512 / GBN, NROWS / GBM), 256>>>(pAV1 + 512, 1024, pWf2mT, 512, pQ1 + 512, 1024, pbf2m, 16);

    // attention layer 2 with fused sequence-sum -> g_part
    attn_kernel<NCULT,  true><<<512, 256, smemC>>>(pQ1, 1024, 0,   pKc, pVc, cmask, nullptr, 0, 0, pPart);
    attn_kernel<NMORAL, true><<<512, 256, smemM>>>(pQ1, 1024, 512, pKm, pVm, mmask, nullptr, 0, 0,
                                                   pPart + (size_t)BATCH * 16 * 512);

    final_kernel<<<BATCH, 512>>>(cWo, cbo, mWo, mbo, out);
}

// round 5
// speedup vs baseline: 5.9695x; 3.7990x over previous
#include <cuda_runtime.h>
#include <cuda_bf16.h>
#include <cstdint>

// ---------------- problem constants ----------------
#define BATCH 32
#define SEQ   2048
#define NROWS (BATCH*SEQ)   // 65536
#define NP 256              // packed columns: 8 head-groups x (19 cult | 10 moral | 3 pad)

// ---------------- scratch (device globals) ----------------
__device__ __nv_bfloat16 g_emb16[(size_t)NROWS*1024];  // 128MB
__device__ __nv_bfloat16 g_W1[(size_t)NROWS*NP];       // 32MB  layer-1 attention weights
__device__ __nv_bfloat16 g_P1T[NP*1024];               // B of pass 1: [n][k]
__device__ __nv_bfloat16 g_GT[NP*NP];                  // B of pass 2: GT[n_out][n_in]
__device__ float g_KQ[512*NP];                         // KQ[e][n] = sum_d Wq[e,d]K[j,d]/8
__device__ float g_VW[NP*512];                         // VWo[n][f] = sum_{e in head} V[j,e]Wo[e,f]
__device__ float g_VWq[NP*512];                        // VWo @ Wq
__device__ float g_beta1[NP], g_beta2[NP];
__device__ float g_Kc[19*512], g_Vc[19*512], g_Km[10*512], g_Vm[10*512];
__device__ float g_bf1[1024];                          // [b_lin@cWq+cbq | b_lin@mWq+mbq]
__device__ float g_bf2c[512], g_bf2m[512];             // bo@Wq+bq per branch
__device__ float g_pmsum[BATCH];
__device__ float g_part[512*NP];                       // per row-block column sums of w2

__device__ __forceinline__ uint32_t smem_u32(const void* p) {
    return (uint32_t)__cvta_generic_to_shared(p);
}
__device__ __forceinline__ void cp_async16(uint32_t dst, const void* src) {
    asm volatile("cp.async.cg.shared.global [%0], [%1], 16;" :: "r"(dst), "l"(src));
}
__device__ __forceinline__ uint32_t sw128(uint32_t b) { return b ^ ((b >> 3) & 0x70u); }

// ===================================================================
// prep: K/V head tables + folded bias rows (exact fp32)
// ===================================================================
__global__ void prep_rows(const float* __restrict__ ctab, const float* __restrict__ mtab,
                          const float* __restrict__ cWk, const float* __restrict__ cbk,
                          const float* __restrict__ cWv, const float* __restrict__ cbv,
                          const float* __restrict__ mWk, const float* __restrict__ mbk,
                          const float* __restrict__ mWv, const float* __restrict__ mbv,
                          const float* __restrict__ b_lin,
                          const float* __restrict__ cWq, const float* __restrict__ cbq,
                          const float* __restrict__ mWq, const float* __restrict__ mbq,
                          const float* __restrict__ cbo, const float* __restrict__ mbo)
{
    const int id = blockIdx.x;
    const float* arow; const float* W; const float* bb; float* out;
    if      (id < 19)  { arow = ctab + id * 512;        W = cWk; bb = cbk; out = g_Kc + id * 512; }
    else if (id < 38)  { arow = ctab + (id - 19) * 512; W = cWv; bb = cbv; out = g_Vc + (id - 19) * 512; }
    else if (id < 48)  { arow = mtab + (id - 38) * 512; W = mWk; bb = mbk; out = g_Km + (id - 38) * 512; }
    else if (id < 58)  { arow = mtab + (id - 48) * 512; W = mWv; bb = mbv; out = g_Vm + (id - 48) * 512; }
    else if (id == 58) { arow = b_lin; W = cWq; bb = cbq; out = g_bf1; }
    else if (id == 59) { arow = b_lin; W = mWq; bb = mbq; out = g_bf1 + 512; }
    else if (id == 60) { arow = cbo;   W = cWq; bb = cbq; out = g_bf2c; }
    else               { arow = mbo;   W = mWq; bb = mbq; out = g_bf2m; }

    __shared__ float sA[512];
    const int c = threadIdx.x;
    sA[c] = arow[c];
    __syncthreads();
    float acc = bb[c];
    for (int k = 0; k < 512; k++) acc += sA[k] * W[k * 512 + c];
    out[c] = acc;
}

__global__ void pmsum_kernel(const int* __restrict__ em, const int* __restrict__ pmask)
{
    __shared__ int sred[8];
    const int b = blockIdx.x, t = threadIdx.x;
    int cnt = 0;
    for (int s = t; s < SEQ; s += 256) cnt += em[b * SEQ + s] * pmask[b * SEQ + s];
#pragma unroll
    for (int st = 16; st; st >>= 1) cnt += __shfl_xor_sync(0xffffffffu, cnt, st);
    if ((t & 31) == 0) sred[t >> 5] = cnt;
    __syncthreads();
    if (t == 0) { int tot = 0; for (int w = 0; w < 8; w++) tot += sred[w]; g_pmsum[b] = (float)tot; }
}

// VWo[n][f] = sum_{e<64} V_br[j, g*64+e] * Wo_br[g*64+e, f]
__global__ void vwo_kernel(const float* __restrict__ cWo, const float* __restrict__ mWo)
{
    const int n = blockIdx.x, g = n >> 5, t = n & 31;
    __shared__ float sv[64];
    const bool pad = (t >= 29);
    const float* V; const float* Wo; int j;
    if (t < 19)      { V = g_Vc; Wo = cWo; j = t; }
    else if (t < 29) { V = g_Vm; Wo = mWo; j = t - 19; }
    else             { V = g_Vc; Wo = cWo; j = 0; }
    const int f = threadIdx.x;                 // 512
    if (f < 64) sv[f] = V[j * 512 + g * 64 + f];
    __syncthreads();
    float acc = 0.f;
    for (int e = 0; e < 64; e++) acc += sv[e] * Wo[(g * 64 + e) * 512 + f];
    g_VW[n * 512 + f] = pad ? 0.f : acc;
}

// VWq[n][d] = sum_f VWo[n][f] * Wq_br[f][d]
__global__ void vwq_kernel(const float* __restrict__ cWq, const float* __restrict__ mWq)
{
    const int n = blockIdx.x, t = n & 31;
    __shared__ float sv[512];
    const float* Wq = (t < 19) ? cWq : mWq;
    const int d = threadIdx.x;                 // 512
    sv[d] = g_VW[n * 512 + d];
    __syncthreads();
    float acc = 0.f;
    for (int f = 0; f < 512; f++) acc += sv[f] * Wq[f * 512 + d];
    g_VWq[n * 512 + d] = acc;                  // pad rows of VW are 0 -> 0
}

// GT[n_out][n_in] = branch-matched: sum_{d<64} VWq[n_in][g*64+d] * K[j, g*64+d] / 8
__global__ void gbuild_kernel()
{
    const int no = blockIdx.x, g = no >> 5, t = no & 31;
    __shared__ float kr[64];
    const bool pad = (t >= 29), cult = (t < 19);
    const float* K = cult ? g_Kc : g_Km;
    int j = cult ? t : (t - 19);
    if (pad) { K = g_Kc; j = 0; }
    const int np = threadIdx.x;                // 256
    if (np < 64) kr[np] = K[j * 512 + g * 64 + np];
    __syncthreads();
    const int tp = np & 31;
    const bool cultp = (tp < 19), padp = (tp >= 29);
    float acc = 0.f;
    for (int d = 0; d < 64; d++) acc += g_VWq[np * 512 + g * 64 + d] * kr[d];
    acc *= 0.125f;
    const bool ok = !pad && !padp && (cult == cultp);
    g_GT[no * 256 + np] = __float2bfloat16(ok ? acc : 0.f);
}

// KQ[e][n] = sum_{d<64} Wq_br[e, g*64+d] * K_br[j, g*64+d] / 8
__global__ void kq_kernel(const float* __restrict__ cWq, const float* __restrict__ mWq)
{
    const int e = blockIdx.x;                  // 512
    __shared__ float swc[512], swm[512];
    const int tid = threadIdx.x;               // 256
    for (int i = tid; i < 512; i += 256) { swc[i] = cWq[e * 512 + i]; swm[i] = mWq[e * 512 + i]; }
    __syncthreads();
    const int n = tid, g = n >> 5, t = n & 31;
    float acc = 0.f;
    if (t < 19) {
        for (int d = 0; d < 64; d++) acc += swc[g * 64 + d] * g_Kc[t * 512 + g * 64 + d];
    } else if (t < 29) {
        const int j = t - 19;
        for (int d = 0; d < 64; d++) acc += swm[g * 64 + d] * g_Km[j * 512 + g * 64 + d];
    }
    g_KQ[e * 256 + n] = acc * 0.125f;
}

// P1T[n][k] = sum_e W_lin[k,e] * KQ[e][n]   (8 k-rows per block)
__global__ void p1_kernel(const float* __restrict__ W_lin)
{
    const int k0 = blockIdx.x * 8;
    __shared__ float sw[8][512];
    const int tid = threadIdx.x;               // 256
    for (int i = tid; i < 8 * 512; i += 256)
        sw[i >> 9][i & 511] = W_lin[(size_t)(k0 + (i >> 9)) * 512 + (i & 511)];
    __syncthreads();
    float acc[8] = {0, 0, 0, 0, 0, 0, 0, 0};
    for (int e = 0; e < 512; e++) {
        const float kq = g_KQ[e * 256 + tid];
#pragma unroll
        for (int r = 0; r < 8; r++) acc[r] += sw[r][e] * kq;
    }
#pragma unroll
    for (int r = 0; r < 8; r++) g_P1T[(size_t)tid * 1024 + k0 + r] = __float2bfloat16(acc[r]);
}

// beta1[n], beta2[n]
__global__ void betas_kernel()
{
    const int n = threadIdx.x, g = n >> 5, t = n & 31;
    float b1 = 0.f, b2 = 0.f;
    if (t < 19) {
        for (int d = 0; d < 64; d++) {
            const float kk = g_Kc[t * 512 + g * 64 + d];
            b1 += g_bf1[g * 64 + d] * kk;
            b2 += g_bf2c[g * 64 + d] * kk;
        }
    } else if (t < 29) {
        const int j = t - 19;
        for (int d = 0; d < 64; d++) {
            const float kk = g_Km[j * 512 + g * 64 + d];
            b1 += g_bf1[512 + g * 64 + d] * kk;
            b2 += g_bf2m[g * 64 + d] * kk;
        }
    }
    g_beta1[n] = b1 * 0.125f;
    g_beta2[n] = b2 * 0.125f;
}

// fp32 -> bf16 (embeddings)
__global__ void conv_bf16_kernel(const float4* __restrict__ in, uint4* __restrict__ out, int n16)
{
    int i = blockIdx.x * blockDim.x + threadIdx.x;
    const int stride = gridDim.x * blockDim.x;
    for (; i < n16; i += stride) {
        float4 a = in[2 * i], b = in[2 * i + 1];
        __nv_bfloat162 h0 = __floats2bfloat162_rn(a.x, a.y);
        __nv_bfloat162 h1 = __floats2bfloat162_rn(a.z, a.w);
        __nv_bfloat162 h2 = __floats2bfloat162_rn(b.x, b.y);
        __nv_bfloat162 h3 = __floats2bfloat162_rn(b.z, b.w);
        out[i] = make_uint4(*reinterpret_cast<uint32_t*>(&h0), *reinterpret_cast<uint32_t*>(&h1),
                            *reinterpret_cast<uint32_t*>(&h2), *reinterpret_cast<uint32_t*>(&h3));
    }
}

// ===================================================================
// Fused pass: C = A @ B^T + beta + mask -> per-group softmax
//   !COLSUM: store bf16 weights to W1out    (pass 1)
//   COLSUM : column-sum over block rows -> part   (pass 2)
// Tile 128x128, BK=32, 3 stages, 8 warps (2m x 4n), warp tile 64x32.
// Warp's 32 columns = exactly one packed group.
// ===================================================================
#define STG 3
#define STAGE_B 16384
#define SMEMB (STG*STAGE_B + 1024)

template<bool COLSUM>
__global__ __launch_bounds__(256, 2)
void fused_pass(const __nv_bfloat16* __restrict__ A, int lda,
                const __nv_bfloat16* __restrict__ B, int ldb,
                const float* __restrict__ beta,
                const int* __restrict__ cmask, const int* __restrict__ mmask,
                __nv_bfloat16* __restrict__ W1out,
                float* __restrict__ part, int KT)
{
    extern __shared__ __align__(16) char dsm[];
    const uint32_t sbase = (smem_u32(dsm) + 1023u) & ~1023u;
    __shared__ float smk[32];
    __shared__ float spart[2][128];

    const int tid  = threadIdx.x;
    const int warp = tid >> 5, lane = tid & 31;
    const int wm = warp >> 2;        // 0..1
    const int wn = warp & 3;         // 0..3
    const int m0 = blockIdx.y * 128;
    const int n0 = blockIdx.x * 128;
    const int b  = blockIdx.y >> 4;  // batch (16 row-blocks per batch)

    if (tid < 32) {
        float v;
        if (tid < 19)      v = (float)cmask[b * 19 + tid];
        else if (tid < 29) v = (float)mmask[b * 10 + tid - 19];
        else               v = -1e30f;
        smk[tid] = v;
    }

    float acc[4][4][4];
#pragma unroll
    for (int i = 0; i < 4; i++)
#pragma unroll
        for (int j = 0; j < 4; j++)
#pragma unroll
            for (int r = 0; r < 4; r++) acc[i][j][r] = 0.f;

    auto load_stage = [&](int s, int kt) {
        const uint32_t ab = sbase + s * STAGE_B;
        const uint32_t bb = ab + 8192;
        const __nv_bfloat16* Ag = A + kt * 32;
        const __nv_bfloat16* Bg = B + kt * 32;
#pragma unroll
        for (int t = 0; t < 2; t++) {
            int id  = tid + t * 256;
            int row = id >> 2, c = id & 3;
            uint32_t byte = row * 64 + c * 16;
            cp_async16(ab + sw128(byte), Ag + (size_t)(m0 + row) * lda + c * 8);
            cp_async16(bb + sw128(byte), Bg + (size_t)(n0 + row) * ldb + c * 8);
        }
    };

    load_stage(0, 0);
    asm volatile("cp.async.commit_group;");
    load_stage(1, 1);
    asm volatile("cp.async.commit_group;");

    const int a_row = lane & 15;
    const int a_k8  = (lane >> 4) << 3;
    const int b_row = (lane & 7) | ((lane >> 4) << 3);
    const int b_k8  = ((lane >> 3) & 1) << 3;

    for (int kt = 0; kt < KT; kt++) {
        const int buf = kt % STG;
        asm volatile("cp.async.wait_group 1;");
        __syncthreads();
        if (kt + 2 < KT) load_stage((kt + 2) % STG, kt + 2);
        asm volatile("cp.async.commit_group;");

        const uint32_t aS = sbase + buf * STAGE_B;
        const uint32_t bS = aS + 8192;

#pragma unroll
        for (int kk = 0; kk < 2; kk++) {
            uint32_t a[4][4], bfr[2][4];
#pragma unroll
            for (int mt = 0; mt < 4; mt++) {
                uint32_t byte = (uint32_t)(wm * 64 + mt * 16 + a_row) * 64
                              + (uint32_t)(kk * 16 + a_k8) * 2;
                uint32_t ad = aS + sw128(byte);
                asm volatile(
                    "ldmatrix.sync.aligned.m8n8.x4.shared.b16 {%0,%1,%2,%3}, [%4];"
                    : "=r"(a[mt][0]), "=r"(a[mt][1]), "=r"(a[mt][2]), "=r"(a[mt][3])
                    : "r"(ad));
            }
#pragma unroll
            for (int np = 0; np < 2; np++) {
                uint32_t byte = (uint32_t)(wn * 32 + np * 16 + b_row) * 64
                              + (uint32_t)(kk * 16 + b_k8) * 2;
                uint32_t bd = bS + sw128(byte);
                asm volatile(
                    "ldmatrix.sync.aligned.m8n8.x4.shared.b16 {%0,%1,%2,%3}, [%4];"
                    : "=r"(bfr[np][0]), "=r"(bfr[np][1]), "=r"(bfr[np][2]), "=r"(bfr[np][3])
                    : "r"(bd));
            }
#pragma unroll
            for (int mt = 0; mt < 4; mt++)
#pragma unroll
                for (int nt = 0; nt < 4; nt++) {
                    const uint32_t b0 = bfr[nt >> 1][(nt & 1) * 2];
                    const uint32_t b1 = bfr[nt >> 1][(nt & 1) * 2 + 1];
                    asm volatile(
                        "mma.sync.aligned.m16n8k16.row.col.f32.bf16.bf16.f32 "
                        "{%0,%1,%2,%3}, {%4,%5,%6,%7}, {%8,%9}, {%0,%1,%2,%3};"
                        : "+f"(acc[mt][nt][0]), "+f"(acc[mt][nt][1]),
                          "+f"(acc[mt][nt][2]), "+f"(acc[mt][nt][3])
                        : "r"(a[mt][0]), "r"(a[mt][1]), "r"(a[mt][2]), "r"(a[mt][3]),
                          "r"(b0), "r"(b1));
                }
        }
        __syncthreads();
    }

    // ---------------- epilogue: bias + mask + per-group softmax ----------------
    const int g = blockIdx.x * 4 + wn;
    float addv[4][2]; bool isc[4][2];
#pragma unroll
    for (int nt = 0; nt < 4; nt++)
#pragma unroll
        for (int q = 0; q < 2; q++) {
            const int t = nt * 8 + (lane & 3) * 2 + q;
            addv[nt][q] = beta[g * 32 + t] + smk[t];
            isc[nt][q]  = (t < 19);
        }

    float colacc[4][2];
#pragma unroll
    for (int nt = 0; nt < 4; nt++) { colacc[nt][0] = 0.f; colacc[nt][1] = 0.f; }

#pragma unroll
    for (int mt = 0; mt < 4; mt++) {
#pragma unroll
        for (int rr = 0; rr < 2; rr++) {
            float v[4][2];
            float mc = -1e30f, mmx = -1e30f;
#pragma unroll
            for (int nt = 0; nt < 4; nt++)
#pragma unroll
                for (int q = 0; q < 2; q++) {
                    v[nt][q] = acc[mt][nt][rr * 2 + q] + addv[nt][q];
                    if (isc[nt][q]) mc = fmaxf(mc, v[nt][q]);
                    else            mmx = fmaxf(mmx, v[nt][q]);
                }
            mc  = fmaxf(mc,  __shfl_xor_sync(0xffffffffu, mc, 1));
            mc  = fmaxf(mc,  __shfl_xor_sync(0xffffffffu, mc, 2));
            mmx = fmaxf(mmx, __shfl_xor_sync(0xffffffffu, mmx, 1));
            mmx = fmaxf(mmx, __shfl_xor_sync(0xffffffffu, mmx, 2));

            float e[4][2];
            float sc = 0.f, sm = 0.f;
#pragma unroll
            for (int nt = 0; nt < 4; nt++)
#pragma unroll
                for (int q = 0; q < 2; q++) {
                    const float ev = __expf(v[nt][q] - (isc[nt][q] ? mc : mmx));
                    e[nt][q] = ev;
                    if (isc[nt][q]) sc += ev; else sm += ev;
                }
            sc += __shfl_xor_sync(0xffffffffu, sc, 1);
            sc += __shfl_xor_sync(0xffffffffu, sc, 2);
            sm += __shfl_xor_sync(0xffffffffu, sm, 1);
            sm += __shfl_xor_sync(0xffffffffu, sm, 2);
            const float ic = 1.f / sc, im = 1.f / sm;

            if (!COLSUM) {
                const int row = m0 + wm * 64 + mt * 16 + (lane >> 2) + rr * 8;
                __nv_bfloat16* dst = W1out + (size_t)row * NP + g * 32 + (lane & 3) * 2;
#pragma unroll
                for (int nt = 0; nt < 4; nt++) {
                    const float w0 = e[nt][0] * (isc[nt][0] ? ic : im);
                    const float w1 = e[nt][1] * (isc[nt][1] ? ic : im);
                    __nv_bfloat162 h = __floats2bfloat162_rn(w0, w1);
                    *reinterpret_cast<__nv_bfloat162*>(dst + nt * 8) = h;
                }
            } else {
#pragma unroll
                for (int nt = 0; nt < 4; nt++)
#pragma unroll
                    for (int q = 0; q < 2; q++)
                        colacc[nt][q] += e[nt][q] * (isc[nt][q] ? ic : im);
            }
        }
    }

    if (COLSUM) {
#pragma unroll
        for (int st = 4; st < 32; st <<= 1)
#pragma unroll
            for (int nt = 0; nt < 4; nt++) {
                colacc[nt][0] += __shfl_xor_sync(0xffffffffu, colacc[nt][0], st);
                colacc[nt][1] += __shfl_xor_sync(0xffffffffu, colacc[nt][1], st);
            }
        if (lane < 4) {
#pragma unroll
            for (int nt = 0; nt < 4; nt++) {
                spart[wm][wn * 32 + nt * 8 + lane * 2]     = colacc[nt][0];
                spart[wm][wn * 32 + nt * 8 + lane * 2 + 1] = colacc[nt][1];
            }
        }
        __syncthreads();
        if (tid < 128)
            part[(size_t)blockIdx.y * NP + blockIdx.x * 128 + tid] =
                spart[0][tid] + spart[1][tid];
    }
}

// ===================================================================
// final: Wsum = sum of 16 block parts; out = Wsum . VWo / pmsum + S*bo/pmsum
// ===================================================================
__global__ void final_kernel(const float* __restrict__ cbo, const float* __restrict__ mbo,
                             float* __restrict__ out)
{
    __shared__ float ws[NP];
    const int b = blockIdx.x, tid = threadIdx.x;
    if (tid < NP) {
        float s = 0.f;
#pragma unroll
        for (int p = 0; p < 16; p++) s += g_part[(size_t)(b * 16 + p) * NP + tid];
        ws[tid] = s;
    }
    __syncthreads();
    const int c = tid;   // 512 threads
    float oc = 0.f, om = 0.f;
#pragma unroll 1
    for (int g = 0; g < 8; g++) {
#pragma unroll
        for (int t = 0; t < 19; t++) oc += ws[g * 32 + t] * g_VW[(size_t)(g * 32 + t) * 512 + c];
#pragma unroll
        for (int t = 19; t < 29; t++) om += ws[g * 32 + t] * g_VW[(size_t)(g * 32 + t) * 512 + c];
    }
    const float invp = 1.f / g_pmsum[b];
    oc = (oc + 2048.f * cbo[c]) * invp;
    om = (om + 2048.f * mbo[c]) * invp;
    out[b * 512 + c] = oc;
    out[BATCH * 512 + b * 512 + c] = oc - om;
}

// ===================================================================
extern "C" void kernel_launch(void* const* d_in, const int* in_sizes, int n_in,
                              void* d_out, int out_size)
{
    const float* emb   = (const float*)d_in[0];
    const int*   emask = (const int*)d_in[1];
    const int*   pmask = (const int*)d_in[2];
    // d_in[3] frame_mask cancels in softmax — unused
    const int*   cmask = (const int*)d_in[4];
    const int*   mmask = (const int*)d_in[5];
    const float* W_lin = (const float*)d_in[6];
    const float* b_lin = (const float*)d_in[7];
    const float* ctab  = (const float*)d_in[8];
    const float* mtab  = (const float*)d_in[9];
    const float* cWq = (const float*)d_in[10]; const float* cbq = (const float*)d_in[11];
    const float* cWk = (const float*)d_in[12]; const float* cbk = (const float*)d_in[13];
    const float* cWv = (const float*)d_in[14]; const float* cbv = (const float*)d_in[15];
    const float* cWo = (const float*)d_in[16]; const float* cbo = (const float*)d_in[17];
    const float* mWq = (const float*)d_in[18]; const float* mbq = (const float*)d_in[19];
    const float* mWk = (const float*)d_in[20]; const float* mbk = (const float*)d_in[21];
    const float* mWv = (const float*)d_in[22]; const float* mbv = (const float*)d_in[23];
    const float* mWo = (const float*)d_in[24]; const float* mbo = (const float*)d_in[25];
    float* out = (float*)d_out;

    __nv_bfloat16 *pE, *pW1, *pP1T, *pGT;
    float *pbeta1, *pbeta2, *pPart;
    cudaGetSymbolAddress((void**)&pE,     g_emb16);
    cudaGetSymbolAddress((void**)&pW1,    g_W1);
    cudaGetSymbolAddress((void**)&pP1T,   g_P1T);
    cudaGetSymbolAddress((void**)&pGT,    g_GT);
    cudaGetSymbolAddress((void**)&pbeta1, g_beta1);
    cudaGetSymbolAddress((void**)&pbeta2, g_beta2);
    cudaGetSymbolAddress((void**)&pPart,  g_part);

    cudaFuncSetAttribute(fused_pass<false>, cudaFuncAttributeMaxDynamicSharedMemorySize, SMEMB);
    cudaFuncSetAttribute(fused_pass<true>,  cudaFuncAttributeMaxDynamicSharedMemorySize, SMEMB);

    // streaming conversion + small preps (sequential stream dependencies)
    conv_bf16_kernel<<<2048, 256>>>((const float4*)emb, (uint4*)pE, NROWS * 1024 / 8);
    prep_rows<<<62, 512>>>(ctab, mtab, cWk, cbk, cWv, cbv, mWk, mbk, mWv, mbv,
                           b_lin, cWq, cbq, mWq, mbq, cbo, mbo);
    pmsum_kernel<<<BATCH, 256>>>(emask, pmask);
    vwo_kernel<<<256, 512>>>(cWo, mWo);
    vwq_kernel<<<256, 512>>>(cWq, mWq);
    kq_kernel<<<512, 256>>>(cWq, mWq);
    gbuild_kernel<<<256, 256>>>();
    betas_kernel<<<1, 256>>>();
    p1_kernel<<<128, 256>>>(W_lin);

    // pass 1: logits1 + softmax -> W1   [65536 x 256], K = 1024
    fused_pass<false><<<dim3(2, 512), 256, SMEMB>>>(pE, 1024, pP1T, 1024, pbeta1,
                                                    cmask, mmask, pW1, nullptr, 32);
    // pass 2: logits2 + softmax + column-sum -> g_part   K = 256
    fused_pass<true><<<dim3(2, 512), 256, SMEMB>>>(pW1, 256, pGT, 256, pbeta2,
                                                   cmask, mmask, nullptr, pPart, 8);

    final_kernel<<<BATCH, 512>>>(cbo, mbo, out);
}

// round 6
// speedup vs baseline: 6.1415x; 1.0288x over previous
#include <cuda_runtime.h>
#include <cuda_bf16.h>
#include <cstdint>

// ---------------- problem constants ----------------
#define BATCH 32
#define SEQ   2048
#define NROWS (BATCH*SEQ)   // 65536
#define NP 256              // packed columns: 8 head-groups x (19 cult | 10 moral | 3 pad)

// ---------------- scratch (device globals) ----------------
__device__ __nv_bfloat16 g_W1[(size_t)NROWS*NP];       // 32MB  layer-1 attention weights
__device__ __nv_bfloat16 g_P1T[NP*1024];               // B of pass 1: [n][k]
__device__ __nv_bfloat16 g_GT[NP*NP];                  // B of pass 2: GT[n_out][n_in]
__device__ float g_KQ[512*NP];                         // KQ[e][n] = sum_d Wq[e,d]K[j,d]/8
__device__ float g_VW[NP*512];                         // VWo[n][f]
__device__ float g_VWq[NP*512];                        // VWo @ Wq
__device__ float g_beta1[NP], g_beta2[NP];
__device__ float g_Kc[19*512], g_Vc[19*512], g_Km[10*512], g_Vm[10*512];
__device__ float g_bf1[1024];                          // [b_lin@cWq+cbq | b_lin@mWq+mbq]
__device__ float g_bf2c[512], g_bf2m[512];             // bo@Wq+bq per branch
__device__ float g_pmsum[BATCH];
__device__ float g_part[512*NP];                       // per row-block column sums of w2

__device__ __forceinline__ uint32_t smem_u32(const void* p) {
    return (uint32_t)__cvta_generic_to_shared(p);
}
__device__ __forceinline__ void cp_async16(uint32_t dst, const void* src) {
    asm volatile("cp.async.cg.shared.global [%0], [%1], 16;" :: "r"(dst), "l"(src));
}
__device__ __forceinline__ uint32_t sw128(uint32_t b) { return b ^ ((b >> 3) & 0x70u); }
__device__ __forceinline__ uint32_t pk2(float x, float y) {
    __nv_bfloat162 h = __floats2bfloat162_rn(x, y);
    return *reinterpret_cast<uint32_t*>(&h);
}

// ===================================================================
// prep level A: K/V head tables + folded bias rows (ids 0..61) and
//               pmsum (ids 62..93).  512 threads.
// ===================================================================
__global__ void prep_ab(const float* __restrict__ ctab, const float* __restrict__ mtab,
                        const float* __restrict__ cWk, const float* __restrict__ cbk,
                        const float* __restrict__ cWv, const float* __restrict__ cbv,
                        const float* __restrict__ mWk, const float* __restrict__ mbk,
                        const float* __restrict__ mWv, const float* __restrict__ mbv,
                        const float* __restrict__ b_lin,
                        const float* __restrict__ cWq, const float* __restrict__ cbq,
                        const float* __restrict__ mWq, const float* __restrict__ mbq,
                        const float* __restrict__ cbo, const float* __restrict__ mbo,
                        const int* __restrict__ em, const int* __restrict__ pmask)
{
    const int id = blockIdx.x;
    const int tid = threadIdx.x;
    if (id < 62) {
        const float* arow; const float* W; const float* bb; float* out;
        if      (id < 19)  { arow = ctab + id * 512;        W = cWk; bb = cbk; out = g_Kc + id * 512; }
        else if (id < 38)  { arow = ctab + (id - 19) * 512; W = cWv; bb = cbv; out = g_Vc + (id - 19) * 512; }
        else if (id < 48)  { arow = mtab + (id - 38) * 512; W = mWk; bb = mbk; out = g_Km + (id - 38) * 512; }
        else if (id < 58)  { arow = mtab + (id - 48) * 512; W = mWv; bb = mbv; out = g_Vm + (id - 48) * 512; }
        else if (id == 58) { arow = b_lin; W = cWq; bb = cbq; out = g_bf1; }
        else if (id == 59) { arow = b_lin; W = mWq; bb = mbq; out = g_bf1 + 512; }
        else if (id == 60) { arow = cbo;   W = cWq; bb = cbq; out = g_bf2c; }
        else               { arow = mbo;   W = mWq; bb = mbq; out = g_bf2m; }

        __shared__ float sA[512];
        sA[tid] = arow[tid];
        __syncthreads();
        float acc = bb[tid];
        for (int k = 0; k < 512; k++) acc += sA[k] * W[k * 512 + tid];
        out[tid] = acc;
    } else {
        const int b = id - 62;
        __shared__ int sred[16];
        int cnt = 0;
        for (int s = tid; s < SEQ; s += 512) cnt += em[b * SEQ + s] * pmask[b * SEQ + s];
#pragma unroll
        for (int st = 16; st; st >>= 1) cnt += __shfl_xor_sync(0xffffffffu, cnt, st);
        if ((tid & 31) == 0) sred[tid >> 5] = cnt;
        __syncthreads();
        if (tid == 0) {
            int tot = 0;
            for (int w = 0; w < 16; w++) tot += sred[w];
            g_pmsum[b] = (float)tot;
        }
    }
}

// ===================================================================
// prep level B: kq (ids 0..511, e=id) and vwo (ids 512..767). 512 thr.
// ===================================================================
__global__ void prep_b(const float* __restrict__ cWq, const float* __restrict__ mWq,
                       const float* __restrict__ cWo, const float* __restrict__ mWo)
{
    const int id = blockIdx.x;
    const int tid = threadIdx.x;
    if (id < 512) {
        // KQ[e][n] = sum_{d<64} Wq_br[e, g*64+d] * K_br[j, g*64+d] / 8
        const int e = id;
        __shared__ float swc[512], swm[512];
        swc[tid] = cWq[e * 512 + tid];
        swm[tid] = mWq[e * 512 + tid];
        __syncthreads();
        if (tid < 256) {
            const int n = tid, g = n >> 5, t = n & 31;
            float acc = 0.f;
            if (t < 19) {
                for (int d = 0; d < 64; d++) acc += swc[g * 64 + d] * g_Kc[t * 512 + g * 64 + d];
            } else if (t < 29) {
                const int j = t - 19;
                for (int d = 0; d < 64; d++) acc += swm[g * 64 + d] * g_Km[j * 512 + g * 64 + d];
            }
            g_KQ[e * 256 + n] = acc * 0.125f;
        }
    } else {
        // VWo[n][f] = sum_{e<64} V_br[j, g*64+e] * Wo_br[g*64+e, f]
        const int n = id - 512, g = n >> 5, t = n & 31;
        __shared__ float sv[64];
        const bool pad = (t >= 29);
        const float* V; const float* Wo; int j;
        if (t < 19)      { V = g_Vc; Wo = cWo; j = t; }
        else if (t < 29) { V = g_Vm; Wo = mWo; j = t - 19; }
        else             { V = g_Vc; Wo = cWo; j = 0; }
        const int f = tid;
        if (f < 64) sv[f] = V[j * 512 + g * 64 + f];
        __syncthreads();
        float acc = 0.f;
        for (int e = 0; e < 64; e++) acc += sv[e] * Wo[(g * 64 + e) * 512 + f];
        g_VW[n * 512 + f] = pad ? 0.f : acc;
    }
}

// ===================================================================
// prep level C: vwq (ids 0..255) and p1 (ids 256..383). 512 threads.
// ===================================================================
__global__ void prep_c(const float* __restrict__ cWq, const float* __restrict__ mWq,
                       const float* __restrict__ W_lin)
{
    const int id = blockIdx.x;
    const int tid = threadIdx.x;
    if (id < 256) {
        // VWq[n][d] = sum_f VWo[n][f] * Wq_br[f][d]
        const int n = id, t = n & 31;
        __shared__ float sv[512];
        const float* Wq = (t < 19) ? cWq : mWq;
        const int d = tid;
        sv[d] = g_VW[n * 512 + d];
        __syncthreads();
        float acc = 0.f;
        for (int f = 0; f < 512; f++) acc += sv[f] * Wq[f * 512 + d];
        g_VWq[n * 512 + d] = acc;
    } else {
        // P1T[n][k] = sum_e W_lin[k,e] * KQ[e][n]   (8 k-rows per block)
        const int k0 = (id - 256) * 8;
        __shared__ float sw[8][512];
        for (int i = tid; i < 8 * 512; i += 512)
            sw[i >> 9][i & 511] = W_lin[(size_t)(k0 + (i >> 9)) * 512 + (i & 511)];
        __syncthreads();
        if (tid < 256) {
            float acc[8] = {0, 0, 0, 0, 0, 0, 0, 0};
            for (int e = 0; e < 512; e++) {
                const float kq = g_KQ[e * 256 + tid];
#pragma unroll
                for (int r = 0; r < 8; r++) acc[r] += sw[r][e] * kq;
            }
#pragma unroll
            for (int r = 0; r < 8; r++)
                g_P1T[(size_t)tid * 1024 + k0 + r] = __float2bfloat16(acc[r]);
        }
    }
}

// ===================================================================
// prep level D: gbuild (ids 0..255) and betas (id 256). 256 threads.
// ===================================================================
__global__ void prep_d()
{
    const int id = blockIdx.x;
    const int tid = threadIdx.x;
    if (id < 256) {
        // GT[n_out][n_in], branch-matched
        const int no = id, g = no >> 5, t = no & 31;
        __shared__ float kr[64];
        const bool pad = (t >= 29), cult = (t < 19);
        const float* K = cult ? g_Kc : g_Km;
        int j = cult ? t : (t - 19);
        if (pad) { K = g_Kc; j = 0; }
        if (tid < 64) kr[tid] = K[j * 512 + g * 64 + tid];
        __syncthreads();
        const int np = tid;
        const int tp = np & 31;
        const bool cultp = (tp < 19), padp = (tp >= 29);
        float acc = 0.f;
        for (int d = 0; d < 64; d++) acc += g_VWq[np * 512 + g * 64 + d] * kr[d];
        acc *= 0.125f;
        const bool ok = !pad && !padp && (cult == cultp);
        g_GT[no * 256 + np] = __float2bfloat16(ok ? acc : 0.f);
    } else {
        // betas
        const int n = tid, g = n >> 5, t = n & 31;
        float b1 = 0.f, b2 = 0.f;
        if (t < 19) {
            for (int d = 0; d < 64; d++) {
                const float kk = g_Kc[t * 512 + g * 64 + d];
                b1 += g_bf1[g * 64 + d] * kk;
                b2 += g_bf2c[g * 64 + d] * kk;
            }
        } else if (t < 29) {
            const int j = t - 19;
            for (int d = 0; d < 64; d++) {
                const float kk = g_Km[j * 512 + g * 64 + d];
                b1 += g_bf1[512 + g * 64 + d] * kk;
                b2 += g_bf2m[g * 64 + d] * kk;
            }
        }
        g_beta1[n] = b1 * 0.125f;
        g_beta2[n] = b2 * 0.125f;
    }
}

// ===================================================================
// Fused pass: C = A @ B^T + beta + mask -> per-group softmax
//   AF32:  A is fp32 in global; converted to bf16 in-kernel (pass 1)
//   !AF32: A is bf16, cp.async path (pass 2)
//   !COLSUM: store bf16 weights to W1out;  COLSUM: column-sum -> part
// Tile 128x128, BK=32, 8 warps (2m x 4n), warp tile 64x32.
// ===================================================================
#define STG 3
#define STAGE_B 16384
#define SMEM_P1 (3*8192 + 2*8192 + 1024)
#define SMEM_P2 (STG*STAGE_B + 1024)

template<bool COLSUM, bool AF32>
__global__ __launch_bounds__(256, 2)
void fused_pass(const void* __restrict__ Av, int lda,
                const __nv_bfloat16* __restrict__ B, int ldb,
                const float* __restrict__ beta,
                const int* __restrict__ cmask, const int* __restrict__ mmask,
                __nv_bfloat16* __restrict__ W1out,
                float* __restrict__ part, int KT)
{
    extern __shared__ __align__(16) char dsm[];
    const uint32_t sbase = (smem_u32(dsm) + 1023u) & ~1023u;
    __shared__ float smk[32];
    __shared__ float spart[2][128];

    const int tid  = threadIdx.x;
    const int warp = tid >> 5, lane = tid & 31;
    const int wm = warp >> 2;        // 0..1
    const int wn = warp & 3;         // 0..3
    const int m0 = blockIdx.y * 128;
    const int n0 = blockIdx.x * 128;
    const int b  = blockIdx.y >> 4;  // batch

    if (tid < 32) {
        float v;
        if (tid < 19)      v = (float)cmask[b * 19 + tid];
        else if (tid < 29) v = (float)mmask[b * 10 + tid - 19];
        else               v = -1e30f;
        smk[tid] = v;
    }

    float acc[4][4][4];
#pragma unroll
    for (int i = 0; i < 4; i++)
#pragma unroll
        for (int j = 0; j < 4; j++)
#pragma unroll
            for (int r = 0; r < 4; r++) acc[i][j][r] = 0.f;

    const int a_row = lane & 15;
    const int a_k8  = (lane >> 4) << 3;
    const int b_row = (lane & 7) | ((lane >> 4) << 3);
    const int b_k8  = ((lane >> 3) & 1) << 3;

    if constexpr (AF32) {
        // ---------------- pass-1 path: fp32 A via LDG + in-kernel cvt ----------------
        const float* Af = (const float*)Av;
        const uint32_t cb0 = sbase + 3 * 8192;           // 2 x 8KB bf16 A buffers
        const float* aptr = Af + (size_t)(m0 + (tid >> 1)) * lda + (tid & 1) * 16;

        float4 ar0, ar1, ar2, ar3;
        auto ldgA = [&](int kt) {
            const float4* p = (const float4*)(aptr + kt * 32);
            ar0 = p[0]; ar1 = p[1]; ar2 = p[2]; ar3 = p[3];
        };
        auto stsA = [&](int buf) {
            const uint32_t rowb = (uint32_t)(tid >> 1) * 64 + (uint32_t)(tid & 1) * 32;
            const uint32_t a0 = cb0 + buf * 8192 + sw128(rowb);
            const uint32_t a1 = cb0 + buf * 8192 + sw128(rowb + 16);
            uint32_t h0 = pk2(ar0.x, ar0.y), h1 = pk2(ar0.z, ar0.w);
            uint32_t h2 = pk2(ar1.x, ar1.y), h3 = pk2(ar1.z, ar1.w);
            uint32_t h4 = pk2(ar2.x, ar2.y), h5 = pk2(ar2.z, ar2.w);
            uint32_t h6 = pk2(ar3.x, ar3.y), h7 = pk2(ar3.z, ar3.w);
            asm volatile("st.shared.v4.b32 [%0], {%1,%2,%3,%4};"
                         :: "r"(a0), "r"(h0), "r"(h1), "r"(h2), "r"(h3));
            asm volatile("st.shared.v4.b32 [%0], {%1,%2,%3,%4};"
                         :: "r"(a1), "r"(h4), "r"(h5), "r"(h6), "r"(h7));
        };
        auto loadB = [&](int s, int kt) {
            const uint32_t bb = sbase + s * 8192;
            const __nv_bfloat16* Bg = B + kt * 32;
#pragma unroll
            for (int t = 0; t < 2; t++) {
                int id  = tid + t * 256;
                int row = id >> 2, c = id & 3;
                uint32_t byte = row * 64 + c * 16;
                cp_async16(bb + sw128(byte), Bg + (size_t)(n0 + row) * ldb + c * 8);
            }
        };

        ldgA(0);
        loadB(0, 0);
        asm volatile("cp.async.commit_group;");
        loadB(1, 1);
        asm volatile("cp.async.commit_group;");

        for (int kt = 0; kt < KT; kt++) {
            stsA(kt & 1);
            if (kt + 1 < KT) ldgA(kt + 1);
            asm volatile("cp.async.wait_group 1;");
            __syncthreads();
            if (kt + 2 < KT) loadB((kt + 2) % 3, kt + 2);
            asm volatile("cp.async.commit_group;");

            const uint32_t aS = cb0 + (kt & 1) * 8192;
            const uint32_t bS = sbase + (kt % 3) * 8192;
#pragma unroll
            for (int kk = 0; kk < 2; kk++) {
                uint32_t a[4][4], bfr[2][4];
#pragma unroll
                for (int mt = 0; mt < 4; mt++) {
                    uint32_t byte = (uint32_t)(wm * 64 + mt * 16 + a_row) * 64
                                  + (uint32_t)(kk * 16 + a_k8) * 2;
                    uint32_t ad = aS + sw128(byte);
                    asm volatile(
                        "ldmatrix.sync.aligned.m8n8.x4.shared.b16 {%0,%1,%2,%3}, [%4];"
                        : "=r"(a[mt][0]), "=r"(a[mt][1]), "=r"(a[mt][2]), "=r"(a[mt][3])
                        : "r"(ad));
                }
#pragma unroll
                for (int np = 0; np < 2; np++) {
                    uint32_t byte = (uint32_t)(wn * 32 + np * 16 + b_row) * 64
                                  + (uint32_t)(kk * 16 + b_k8) * 2;
                    uint32_t bd = bS + sw128(byte);
                    asm volatile(
                        "ldmatrix.sync.aligned.m8n8.x4.shared.b16 {%0,%1,%2,%3}, [%4];"
                        : "=r"(bfr[np][0]), "=r"(bfr[np][1]), "=r"(bfr[np][2]), "=r"(bfr[np][3])
                        : "r"(bd));
                }
#pragma unroll
                for (int mt = 0; mt < 4; mt++)
#pragma unroll
                    for (int nt = 0; nt < 4; nt++) {
                        const uint32_t b0 = bfr[nt >> 1][(nt & 1) * 2];
                        const uint32_t b1 = bfr[nt >> 1][(nt & 1) * 2 + 1];
                        asm volatile(
                            "mma.sync.aligned.m16n8k16.row.col.f32.bf16.bf16.f32 "
                            "{%0,%1,%2,%3}, {%4,%5,%6,%7}, {%8,%9}, {%0,%1,%2,%3};"
                            : "+f"(acc[mt][nt][0]), "+f"(acc[mt][nt][1]),
                              "+f"(acc[mt][nt][2]), "+f"(acc[mt][nt][3])
                            : "r"(a[mt][0]), "r"(a[mt][1]), "r"(a[mt][2]), "r"(a[mt][3]),
                              "r"(b0), "r"(b1));
                    }
            }
            __syncthreads();
        }
    } else {
        // ---------------- pass-2 path: bf16 A via cp.async (R5 pipeline) ----------------
        const __nv_bfloat16* Ab = (const __nv_bfloat16*)Av;
        auto load_stage = [&](int s, int kt) {
            const uint32_t ab = sbase + s * STAGE_B;
            const uint32_t bb = ab + 8192;
            const __nv_bfloat16* Ag = Ab + kt * 32;
            const __nv_bfloat16* Bg = B + kt * 32;
#pragma unroll
            for (int t = 0; t < 2; t++) {
                int id  = tid + t * 256;
                int row = id >> 2, c = id & 3;
                uint32_t byte = row * 64 + c * 16;
                cp_async16(ab + sw128(byte), Ag + (size_t)(m0 + row) * lda + c * 8);
                cp_async16(bb + sw128(byte), Bg + (size_t)(n0 + row) * ldb + c * 8);
            }
        };

        load_stage(0, 0);
        asm volatile("cp.async.commit_group;");
        load_stage(1, 1);
        asm volatile("cp.async.commit_group;");

        for (int kt = 0; kt < KT; kt++) {
            const int buf = kt % STG;
            asm volatile("cp.async.wait_group 1;");
            __syncthreads();
            if (kt + 2 < KT) load_stage((kt + 2) % STG, kt + 2);
            asm volatile("cp.async.commit_group;");

            const uint32_t aS = sbase + buf * STAGE_B;
            const uint32_t bS = aS + 8192;
#pragma unroll
            for (int kk = 0; kk < 2; kk++) {
                uint32_t a[4][4], bfr[2][4];
#pragma unroll
                for (int mt = 0; mt < 4; mt++) {
                    uint32_t byte = (uint32_t)(wm * 64 + mt * 16 + a_row) * 64
                                  + (uint32_t)(kk * 16 + a_k8) * 2;
                    uint32_t ad = aS + sw128(byte);
                    asm volatile(
                        "ldmatrix.sync.aligned.m8n8.x4.shared.b16 {%0,%1,%2,%3}, [%4];"
                        : "=r"(a[mt][0]), "=r"(a[mt][1]), "=r"(a[mt][2]), "=r"(a[mt][3])
                        : "r"(ad));
                }
#pragma unroll
                for (int np = 0; np < 2; np++) {
                    uint32_t byte = (uint32_t)(wn * 32 + np * 16 + b_row) * 64
                                  + (uint32_t)(kk * 16 + b_k8) * 2;
                    uint32_t bd = bS + sw128(byte);
                    asm volatile(
                        "ldmatrix.sync.aligned.m8n8.x4.shared.b16 {%0,%1,%2,%3}, [%4];"
                        : "=r"(bfr[np][0]), "=r"(bfr[np][1]), "=r"(bfr[np][2]), "=r"(bfr[np][3])
                        : "r"(bd));
                }
#pragma unroll
                for (int mt = 0; mt < 4; mt++)
#pragma unroll
                    for (int nt = 0; nt < 4; nt++) {
                        const uint32_t b0 = bfr[nt >> 1][(nt & 1) * 2];
                        const uint32_t b1 = bfr[nt >> 1][(nt & 1) * 2 + 1];
                        asm volatile(
                            "mma.sync.aligned.m16n8k16.row.col.f32.bf16.bf16.f32 "
                            "{%0,%1,%2,%3}, {%4,%5,%6,%7}, {%8,%9}, {%0,%1,%2,%3};"
                            : "+f"(acc[mt][nt][0]), "+f"(acc[mt][nt][1]),
                              "+f"(acc[mt][nt][2]), "+f"(acc[mt][nt][3])
                            : "r"(a[mt][0]), "r"(a[mt][1]), "r"(a[mt][2]), "r"(a[mt][3]),
                              "r"(b0), "r"(b1));
                    }
            }
            __syncthreads();
        }
    }

    // ---------------- epilogue: bias + mask + per-group softmax ----------------
    const int g = blockIdx.x * 4 + wn;
    float addv[4][2]; bool isc[4][2];
#pragma unroll
    for (int nt = 0; nt < 4; nt++)
#pragma unroll
        for (int q = 0; q < 2; q++) {
            const int t = nt * 8 + (lane & 3) * 2 + q;
            addv[nt][q] = beta[g * 32 + t] + smk[t];
            isc[nt][q]  = (t < 19);
        }

    float colacc[4][2];
#pragma unroll
    for (int nt = 0; nt < 4; nt++) { colacc[nt][0] = 0.f; colacc[nt][1] = 0.f; }

#pragma unroll
    for (int mt = 0; mt < 4; mt++) {
#pragma unroll
        for (int rr = 0; rr < 2; rr++) {
            float v[4][2];
            float mc = -1e30f, mmx = -1e30f;
#pragma unroll
            for (int nt = 0; nt < 4; nt++)
#pragma unroll
                for (int q = 0; q < 2; q++) {
                    v[nt][q] = acc[mt][nt][rr * 2 + q] + addv[nt][q];
                    if (isc[nt][q]) mc = fmaxf(mc, v[nt][q]);
                    else            mmx = fmaxf(mmx, v[nt][q]);
                }
            mc  = fmaxf(mc,  __shfl_xor_sync(0xffffffffu, mc, 1));
            mc  = fmaxf(mc,  __shfl_xor_sync(0xffffffffu, mc, 2));
            mmx = fmaxf(mmx, __shfl_xor_sync(0xffffffffu, mmx, 1));
            mmx = fmaxf(mmx, __shfl_xor_sync(0xffffffffu, mmx, 2));

            float e[4][2];
            float sc = 0.f, sm = 0.f;
#pragma unroll
            for (int nt = 0; nt < 4; nt++)
#pragma unroll
                for (int q = 0; q < 2; q++) {
                    const float ev = __expf(v[nt][q] - (isc[nt][q] ? mc : mmx));
                    e[nt][q] = ev;
                    if (isc[nt][q]) sc += ev; else sm += ev;
                }
            sc += __shfl_xor_sync(0xffffffffu, sc, 1);
            sc += __shfl_xor_sync(0xffffffffu, sc, 2);
            sm += __shfl_xor_sync(0xffffffffu, sm, 1);
            sm += __shfl_xor_sync(0xffffffffu, sm, 2);
            const float ic = 1.f / sc, im = 1.f / sm;

            if (!COLSUM) {
                const int row = m0 + wm * 64 + mt * 16 + (lane >> 2) + rr * 8;
                __nv_bfloat16* dst = W1out + (size_t)row * NP + g * 32 + (lane & 3) * 2;
#pragma unroll
                for (int nt = 0; nt < 4; nt++) {
                    const float w0 = e[nt][0] * (isc[nt][0] ? ic : im);
                    const float w1 = e[nt][1] * (isc[nt][1] ? ic : im);
                    __nv_bfloat162 h = __floats2bfloat162_rn(w0, w1);
                    *reinterpret_cast<__nv_bfloat162*>(dst + nt * 8) = h;
                }
            } else {
#pragma unroll
                for (int nt = 0; nt < 4; nt++)
#pragma unroll
                    for (int q = 0; q < 2; q++)
                        colacc[nt][q] += e[nt][q] * (isc[nt][q] ? ic : im);
            }
        }
    }

    if (COLSUM) {
#pragma unroll
        for (int st = 4; st < 32; st <<= 1)
#pragma unroll
            for (int nt = 0; nt < 4; nt++) {
                colacc[nt][0] += __shfl_xor_sync(0xffffffffu, colacc[nt][0], st);
                colacc[nt][1] += __shfl_xor_sync(0xffffffffu, colacc[nt][1], st);
            }
        if (lane < 4) {
#pragma unroll
            for (int nt = 0; nt < 4; nt++) {
                spart[wm][wn * 32 + nt * 8 + lane * 2]     = colacc[nt][0];
                spart[wm][wn * 32 + nt * 8 + lane * 2 + 1] = colacc[nt][1];
            }
        }
        __syncthreads();
        if (tid < 128)
            part[(size_t)blockIdx.y * NP + blockIdx.x * 128 + tid] =
                spart[0][tid] + spart[1][tid];
    }
}

// ===================================================================
// final: Wsum = sum of 16 block parts; out = Wsum . VWo / pmsum + S*bo/pmsum
// ===================================================================
__global__ void final_kernel(const float* __restrict__ cbo, const float* __restrict__ mbo,
                             float* __restrict__ out)
{
    __shared__ float ws[NP];
    const int b = blockIdx.x, tid = threadIdx.x;
    if (tid < NP) {
        float s = 0.f;
#pragma unroll
        for (int p = 0; p < 16; p++) s += g_part[(size_t)(b * 16 + p) * NP + tid];
        ws[tid] = s;
    }
    __syncthreads();
    const int c = tid;   // 512 threads
    float oc = 0.f, om = 0.f;
#pragma unroll 1
    for (int g = 0; g < 8; g++) {
#pragma unroll
        for (int t = 0; t < 19; t++) oc += ws[g * 32 + t] * g_VW[(size_t)(g * 32 + t) * 512 + c];
#pragma unroll
        for (int t = 19; t < 29; t++) om += ws[g * 32 + t] * g_VW[(size_t)(g * 32 + t) * 512 + c];
    }
    const float invp = 1.f / g_pmsum[b];
    oc = (oc + 2048.f * cbo[c]) * invp;
    om = (om + 2048.f * mbo[c]) * invp;
    out[b * 512 + c] = oc;
    out[BATCH * 512 + b * 512 + c] = oc - om;
}

// ===================================================================
extern "C" void kernel_launch(void* const* d_in, const int* in_sizes, int n_in,
                              void* d_out, int out_size)
{
    const float* emb   = (const float*)d_in[0];
    const int*   emask = (const int*)d_in[1];
    const int*   pmask = (const int*)d_in[2];
    // d_in[3] frame_mask cancels in softmax — unused
    const int*   cmask = (const int*)d_in[4];
    const int*   mmask = (const int*)d_in[5];
    const float* W_lin = (const float*)d_in[6];
    const float* b_lin = (const float*)d_in[7];
    const float* ctab  = (const float*)d_in[8];
    const float* mtab  = (const float*)d_in[9];
    const float* cWq = (const float*)d_in[10]; const float* cbq = (const float*)d_in[11];
    const float* cWk = (const float*)d_in[12]; const float* cbk = (const float*)d_in[13];
    const float* cWv = (const float*)d_in[14]; const float* cbv = (const float*)d_in[15];
    const float* cWo = (const float*)d_in[16]; const float* cbo = (const float*)d_in[17];
    const float* mWq = (const float*)d_in[18]; const float* mbq = (const float*)d_in[19];
    const float* mWk = (const float*)d_in[20]; const float* mbk = (const float*)d_in[21];
    const float* mWv = (const float*)d_in[22]; const float* mbv = (const float*)d_in[23];
    const float* mWo = (const float*)d_in[24]; const float* mbo = (const float*)d_in[25];
    float* out = (float*)d_out;

    __nv_bfloat16 *pW1, *pP1T, *pGT;
    float *pbeta1, *pbeta2, *pPart;
    cudaGetSymbolAddress((void**)&pW1,    g_W1);
    cudaGetSymbolAddress((void**)&pP1T,   g_P1T);
    cudaGetSymbolAddress((void**)&pGT,    g_GT);
    cudaGetSymbolAddress((void**)&pbeta1, g_beta1);
    cudaGetSymbolAddress((void**)&pbeta2, g_beta2);
    cudaGetSymbolAddress((void**)&pPart,  g_part);

    cudaFuncSetAttribute((const void*)fused_pass<false, true>,
                         cudaFuncAttributeMaxDynamicSharedMemorySize, SMEM_P1);
    cudaFuncSetAttribute((const void*)fused_pass<true, false>,
                         cudaFuncAttributeMaxDynamicSharedMemorySize, SMEM_P2);

    // prep chain (4 launches, by dependency level)
    prep_ab<<<94, 512>>>(ctab, mtab, cWk, cbk, cWv, cbv, mWk, mbk, mWv, mbv,
                         b_lin, cWq, cbq, mWq, mbq, cbo, mbo, emask, pmask);
    prep_b<<<768, 512>>>(cWq, mWq, cWo, mWo);
    prep_c<<<384, 512>>>(cWq, mWq, W_lin);
    prep_d<<<257, 256>>>();

    // pass 1: fp32 emb -> logits1 + softmax -> W1 (bf16)   K = 1024
    fused_pass<false, true><<<dim3(2, 512), 256, SMEM_P1>>>(emb, 1024, pP1T, 1024, pbeta1,
                                                            cmask, mmask, pW1, nullptr, 32);
    // pass 2: logits2 + softmax + column-sum -> g_part     K = 256
    fused_pass<true, false><<<dim3(2, 512), 256, SMEM_P2>>>(pW1, 256, pGT, 256, pbeta2,
                                                            cmask, mmask, nullptr, pPart, 8);

    final_kernel<<<BATCH, 512>>>(cbo, mbo, out);
}

// round 7
// speedup vs baseline: 6.4000x; 1.0421x over previous
#include <cuda_runtime.h>
#include <cuda_bf16.h>
#include <cstdint>

// ---------------- problem constants ----------------
#define BATCH 32
#define SEQ   2048
#define NROWS (BATCH*SEQ)   // 65536
#define NP 256              // packed columns: 8 head-groups x (19 cult | 10 moral | 3 pad)

// ---------------- scratch (device globals) ----------------
__device__ __nv_bfloat16 g_P1T[NP*1024];               // B of pass 1: [n][k]
__device__ __nv_bfloat16 g_GT[NP*NP];                  // B of pass 2: GT[n_out][n_in]
__device__ float g_KQ[512*NP];
__device__ float g_VW[NP*512];
__device__ float g_VWq[NP*512];
__device__ float g_beta1[NP], g_beta2[NP];
__device__ float g_Kc[19*512], g_Vc[19*512], g_Km[10*512], g_Vm[10*512];
__device__ float g_bf1[1024];
__device__ float g_bf2c[512], g_bf2m[512];
__device__ float g_pmsum[BATCH];
__device__ float g_part[512*NP];

__device__ __forceinline__ uint32_t smem_u32(const void* p) {
    return (uint32_t)__cvta_generic_to_shared(p);
}
__device__ __forceinline__ void cp_async16(uint32_t dst, const void* src) {
    asm volatile("cp.async.cg.shared.global [%0], [%1], 16;" :: "r"(dst), "l"(src));
}
__device__ __forceinline__ uint32_t sw128(uint32_t b) { return b ^ ((b >> 3) & 0x70u); }
__device__ __forceinline__ uint32_t pk2(float x, float y) {
    __nv_bfloat162 h = __floats2bfloat162_rn(x, y);
    return *reinterpret_cast<uint32_t*>(&h);
}

// ===================================================================
// prep level A: K/V head tables + folded bias rows + pmsum
// ===================================================================
__global__ void prep_ab(const float* __restrict__ ctab, const float* __restrict__ mtab,
                        const float* __restrict__ cWk, const float* __restrict__ cbk,
                        const float* __restrict__ cWv, const float* __restrict__ cbv,
                        const float* __restrict__ mWk, const float* __restrict__ mbk,
                        const float* __restrict__ mWv, const float* __restrict__ mbv,
                        const float* __restrict__ b_lin,
                        const float* __restrict__ cWq, const float* __restrict__ cbq,
                        const float* __restrict__ mWq, const float* __restrict__ mbq,
                        const float* __restrict__ cbo, const float* __restrict__ mbo,
                        const int* __restrict__ em, const int* __restrict__ pmask)
{
    const int id = blockIdx.x;
    const int tid = threadIdx.x;
    if (id < 62) {
        const float* arow; const float* W; const float* bb; float* out;
        if      (id < 19)  { arow = ctab + id * 512;        W = cWk; bb = cbk; out = g_Kc + id * 512; }
        else if (id < 38)  { arow = ctab + (id - 19) * 512; W = cWv; bb = cbv; out = g_Vc + (id - 19) * 512; }
        else if (id < 48)  { arow = mtab + (id - 38) * 512; W = mWk; bb = mbk; out = g_Km + (id - 38) * 512; }
        else if (id < 58)  { arow = mtab + (id - 48) * 512; W = mWv; bb = mbv; out = g_Vm + (id - 48) * 512; }
        else if (id == 58) { arow = b_lin; W = cWq; bb = cbq; out = g_bf1; }
        else if (id == 59) { arow = b_lin; W = mWq; bb = mbq; out = g_bf1 + 512; }
        else if (id == 60) { arow = cbo;   W = cWq; bb = cbq; out = g_bf2c; }
        else               { arow = mbo;   W = mWq; bb = mbq; out = g_bf2m; }

        __shared__ float sA[512];
        sA[tid] = arow[tid];
        __syncthreads();
        float acc = bb[tid];
        for (int k = 0; k < 512; k++) acc += sA[k] * W[k * 512 + tid];
        out[tid] = acc;
    } else {
        const int b = id - 62;
        __shared__ int sred[16];
        int cnt = 0;
        for (int s = tid; s < SEQ; s += 512) cnt += em[b * SEQ + s] * pmask[b * SEQ + s];
#pragma unroll
        for (int st = 16; st; st >>= 1) cnt += __shfl_xor_sync(0xffffffffu, cnt, st);
        if ((tid & 31) == 0) sred[tid >> 5] = cnt;
        __syncthreads();
        if (tid == 0) {
            int tot = 0;
            for (int w = 0; w < 16; w++) tot += sred[w];
            g_pmsum[b] = (float)tot;
        }
    }
}

// ===================================================================
// prep level B: kq (ids 0..511) and vwo (ids 512..767)
// ===================================================================
__global__ void prep_b(const float* __restrict__ cWq, const float* __restrict__ mWq,
                       const float* __restrict__ cWo, const float* __restrict__ mWo)
{
    const int id = blockIdx.x;
    const int tid = threadIdx.x;
    if (id < 512) {
        const int e = id;
        __shared__ float swc[512], swm[512];
        swc[tid] = cWq[e * 512 + tid];
        swm[tid] = mWq[e * 512 + tid];
        __syncthreads();
        if (tid < 256) {
            const int n = tid, g = n >> 5, t = n & 31;
            float acc = 0.f;
            if (t < 19) {
                for (int d = 0; d < 64; d++) acc += swc[g * 64 + d] * g_Kc[t * 512 + g * 64 + d];
            } else if (t < 29) {
                const int j = t - 19;
                for (int d = 0; d < 64; d++) acc += swm[g * 64 + d] * g_Km[j * 512 + g * 64 + d];
            }
            g_KQ[e * 256 + n] = acc * 0.125f;
        }
    } else {
        const int n = id - 512, g = n >> 5, t = n & 31;
        __shared__ float sv[64];
        const bool pad = (t >= 29);
        const float* V; const float* Wo; int j;
        if (t < 19)      { V = g_Vc; Wo = cWo; j = t; }
        else if (t < 29) { V = g_Vm; Wo = mWo; j = t - 19; }
        else             { V = g_Vc; Wo = cWo; j = 0; }
        const int f = tid;
        if (f < 64) sv[f] = V[j * 512 + g * 64 + f];
        __syncthreads();
        float acc = 0.f;
        for (int e = 0; e < 64; e++) acc += sv[e] * Wo[(g * 64 + e) * 512 + f];
        g_VW[n * 512 + f] = pad ? 0.f : acc;
    }
}

// ===================================================================
// prep level C: vwq (ids 0..255) and p1 (ids 256..383)
// ===================================================================
__global__ void prep_c(const float* __restrict__ cWq, const float* __restrict__ mWq,
                       const float* __restrict__ W_lin)
{
    const int id = blockIdx.x;
    const int tid = threadIdx.x;
    if (id < 256) {
        const int n = id, t = n & 31;
        __shared__ float sv[512];
        const float* Wq = (t < 19) ? cWq : mWq;
        const int d = tid;
        sv[d] = g_VW[n * 512 + d];
        __syncthreads();
        float acc = 0.f;
        for (int f = 0; f < 512; f++) acc += sv[f] * Wq[f * 512 + d];
        g_VWq[n * 512 + d] = acc;
    } else {
        const int k0 = (id - 256) * 8;
        __shared__ float sw[8][512];
        for (int i = tid; i < 8 * 512; i += 512)
            sw[i >> 9][i & 511] = W_lin[(size_t)(k0 + (i >> 9)) * 512 + (i & 511)];
        __syncthreads();
        if (tid < 256) {
            float acc[8] = {0, 0, 0, 0, 0, 0, 0, 0};
            for (int e = 0; e < 512; e++) {
                const float kq = g_KQ[e * 256 + tid];
#pragma unroll
                for (int r = 0; r < 8; r++) acc[r] += sw[r][e] * kq;
            }
#pragma unroll
            for (int r = 0; r < 8; r++)
                g_P1T[(size_t)tid * 1024 + k0 + r] = __float2bfloat16(acc[r]);
        }
    }
}

// ===================================================================
// prep level D: gbuild rewritten (coalesced, smem-staged), ids 0..7; betas id 8
// ===================================================================
#define PREPD_SMEM ((256*65 + 32*64) * 4)

__global__ void prep_d()
{
    extern __shared__ float shd[];
    const int id = blockIdx.x;
    const int tid = threadIdx.x;   // 256
    if (id < 8) {
        const int g = id;
        float* vq = shd;              // [256][65]
        float* kr = shd + 256 * 65;   // [32][64]
        for (int i = tid; i < 2048; i += 256) {
            const int t = i >> 6, d = i & 63;
            float val = 0.f;
            if (t < 19)      val = g_Kc[t * 512 + g * 64 + d];
            else if (t < 29) val = g_Km[(t - 19) * 512 + g * 64 + d];
            kr[t * 64 + d] = val;
        }
        for (int i = tid; i < 256 * 64; i += 256) {
            const int np = i >> 6, d = i & 63;
            vq[np * 65 + d] = g_VWq[np * 512 + g * 64 + d];
        }
        __syncthreads();
        const int np = tid;
        const int tp = np & 31;
        const bool cultp = (tp < 19), padp = (tp >= 29);
#pragma unroll 1
        for (int t = 0; t < 32; t++) {
            const bool cult = (t < 19), pad = (t >= 29);
            float acc = 0.f;
#pragma unroll
            for (int d = 0; d < 64; d++) acc += vq[np * 65 + d] * kr[t * 64 + d];
            const bool ok = !pad && !padp && (cult == cultp);
            g_GT[(g * 32 + t) * 256 + np] = __float2bfloat16(ok ? acc * 0.125f : 0.f);
        }
    } else {
        const int n = tid, g = n >> 5, t = n & 31;
        float b1 = 0.f, b2 = 0.f;
        if (t < 19) {
            for (int d = 0; d < 64; d++) {
                const float kk = g_Kc[t * 512 + g * 64 + d];
                b1 += g_bf1[g * 64 + d] * kk;
                b2 += g_bf2c[g * 64 + d] * kk;
            }
        } else if (t < 29) {
            const int j = t - 19;
            for (int d = 0; d < 64; d++) {
                const float kk = g_Km[j * 512 + g * 64 + d];
                b1 += g_bf1[512 + g * 64 + d] * kk;
                b2 += g_bf2m[g * 64 + d] * kk;
            }
        }
        g_beta1[n] = b1 * 0.125f;
        g_beta2[n] = b2 * 0.125f;
    }
}

// ===================================================================
// Fused kernel: one CTA per 128-row tile, 512 threads (16 warps, 4m x 4n).
//  Pass 1: logits1 = emb(fp32->bf16) @ P1T^T, softmax -> W1 SMEM panels.
//  Pass 2: logits2 = W1 @ GT^T (GT cp.async streamed), softmax, colsum -> part.
// SMEM map (dynamic, 1KB-aligned base):
//   [0, 16K)    : A bf16 panels, 2 x 8KB
//   [16K, 64K+16K) : B1 stages, 3 x 16KB   (GT stages 3 x 8KB reuse this)
//   [64K+16K=80K? see offsets below]
// Actual offsets: APAN=0 (16KB), B1=16384 (49152), W1P=65536 (65536). Total 131072.
// ===================================================================
#define SMEM_FUSED (131072 + 1024)

__global__ __launch_bounds__(512, 1)
void fused_all(const float* __restrict__ Af,
               const __nv_bfloat16* __restrict__ P1T,
               const __nv_bfloat16* __restrict__ GT,
               const float* __restrict__ beta1, const float* __restrict__ beta2,
               const int* __restrict__ cmask, const int* __restrict__ mmask,
               float* __restrict__ part)
{
    extern __shared__ __align__(16) char dsm[];
    const uint32_t sbase = (smem_u32(dsm) + 1023u) & ~1023u;
    const uint32_t APAN = sbase;            // 2 x 8KB bf16 A panels
    const uint32_t B1S  = sbase + 16384;    // 3 x 16KB B1 stages / 3 x 8KB GT stages
    const uint32_t W1P  = sbase + 65536;    // 8 x 8KB W1 panels
    __shared__ float smk[32];
    __shared__ float spart[4][NP];

    const int tid  = threadIdx.x;
    const int warp = tid >> 5, lane = tid & 31;
    const int wm = warp >> 2;        // 0..3 -> m offset *32
    const int wn = warp & 3;         // 0..3 -> n offset *64 (pass1) / *32 (pass2 half)
    const int tile = blockIdx.x;
    const int m0 = tile * 128;
    const int b  = tile >> 4;
    const int lq = lane & 3;

    if (tid < 32) {
        float v;
        if (tid < 19)      v = (float)cmask[b * 19 + tid];
        else if (tid < 29) v = (float)mmask[b * 10 + tid - 19];
        else               v = -1e30f;
        smk[tid] = v;
    }

    const int a_row = lane & 15;
    const int a_k8  = (lane >> 4) << 3;
    const int b_row = (lane & 7) | ((lane >> 4) << 3);
    const int b_k8  = ((lane >> 3) & 1) << 3;

    // ================= pass 1 mainloop =================
    float acc1[2][8][4];
#pragma unroll
    for (int i = 0; i < 2; i++)
#pragma unroll
        for (int j = 0; j < 8; j++)
#pragma unroll
            for (int r = 0; r < 4; r++) acc1[i][j][r] = 0.f;

    // A: each thread owns row tid>>2, 8 floats at col (tid&3)*8
    const float* aptr = Af + (size_t)(m0 + (tid >> 2)) * 1024 + (tid & 3) * 8;
    float4 ar0, ar1;
    auto ldgA = [&](int kt) {
        const float4* p = (const float4*)(aptr + kt * 32);
        ar0 = p[0]; ar1 = p[1];
    };
    auto stsA = [&](int buf) {
        const uint32_t byte = (uint32_t)(tid >> 2) * 64 + (uint32_t)(tid & 3) * 16;
        const uint32_t a0 = APAN + buf * 8192 + sw128(byte);
        uint32_t h0 = pk2(ar0.x, ar0.y), h1 = pk2(ar0.z, ar0.w);
        uint32_t h2 = pk2(ar1.x, ar1.y), h3 = pk2(ar1.z, ar1.w);
        asm volatile("st.shared.v4.b32 [%0], {%1,%2,%3,%4};"
                     :: "r"(a0), "r"(h0), "r"(h1), "r"(h2), "r"(h3));
    };
    auto loadB1 = [&](int s, int kt) {
        const uint32_t bb = B1S + s * 16384;
        const __nv_bfloat16* Bg = P1T + kt * 32;
#pragma unroll
        for (int t = 0; t < 2; t++) {
            int id  = tid + t * 512;
            int row = id >> 2, c = id & 3;     // 256 rows x 4 chunks
            uint32_t byte = row * 64 + c * 16;
            cp_async16(bb + sw128(byte), Bg + (size_t)row * 1024 + c * 8);
        }
    };

    ldgA(0);
    loadB1(0, 0);
    asm volatile("cp.async.commit_group;");
    loadB1(1, 1);
    asm volatile("cp.async.commit_group;");

    for (int kt = 0; kt < 32; kt++) {
        stsA(kt & 1);
        if (kt + 1 < 32) ldgA(kt + 1);
        asm volatile("cp.async.wait_group 1;");
        __syncthreads();
        if (kt + 2 < 32) loadB1((kt + 2) % 3, kt + 2);
        asm volatile("cp.async.commit_group;");

        const uint32_t aS = APAN + (kt & 1) * 8192;
        const uint32_t bS = B1S + (kt % 3) * 16384;
#pragma unroll
        for (int kk = 0; kk < 2; kk++) {
            uint32_t a[2][4], bfr[4][4];
#pragma unroll
            for (int mt = 0; mt < 2; mt++) {
                uint32_t byte = (uint32_t)(wm * 32 + mt * 16 + a_row) * 64
                              + (uint32_t)(kk * 16 + a_k8) * 2;
                uint32_t ad = aS + sw128(byte);
                asm volatile(
                    "ldmatrix.sync.aligned.m8n8.x4.shared.b16 {%0,%1,%2,%3}, [%4];"
                    : "=r"(a[mt][0]), "=r"(a[mt][1]), "=r"(a[mt][2]), "=r"(a[mt][3])
                    : "r"(ad));
            }
#pragma unroll
            for (int np = 0; np < 4; np++) {
                uint32_t byte = (uint32_t)(wn * 64 + np * 16 + b_row) * 64
                              + (uint32_t)(kk * 16 + b_k8) * 2;
                uint32_t bd = bS + sw128(byte);
                asm volatile(
                    "ldmatrix.sync.aligned.m8n8.x4.shared.b16 {%0,%1,%2,%3}, [%4];"
                    : "=r"(bfr[np][0]), "=r"(bfr[np][1]), "=r"(bfr[np][2]), "=r"(bfr[np][3])
                    : "r"(bd));
            }
#pragma unroll
            for (int mt = 0; mt < 2; mt++)
#pragma unroll
                for (int nt = 0; nt < 8; nt++) {
                    const uint32_t b0 = bfr[nt >> 1][(nt & 1) * 2];
                    const uint32_t b1v = bfr[nt >> 1][(nt & 1) * 2 + 1];
                    asm volatile(
                        "mma.sync.aligned.m16n8k16.row.col.f32.bf16.bf16.f32 "
                        "{%0,%1,%2,%3}, {%4,%5,%6,%7}, {%8,%9}, {%0,%1,%2,%3};"
                        : "+f"(acc1[mt][nt][0]), "+f"(acc1[mt][nt][1]),
                          "+f"(acc1[mt][nt][2]), "+f"(acc1[mt][nt][3])
                        : "r"(a[mt][0]), "r"(a[mt][1]), "r"(a[mt][2]), "r"(a[mt][3]),
                          "r"(b0), "r"(b1v));
                }
        }
        __syncthreads();
    }

    // ---- prefetch GT stages 0,1 (reuse B1 region) ----
    auto loadGT = [&](int s, int gidx) {
        const int h2 = gidx >> 3, k2 = gidx & 7;
        const uint32_t bb = B1S + s * 8192;
        const int row = tid >> 2, c = tid & 3;   // 128 rows x 4 chunks, 1 per thread
        uint32_t byte = row * 64 + c * 16;
        cp_async16(bb + sw128(byte), GT + (size_t)(h2 * 128 + row) * 256 + k2 * 32 + c * 8);
    };
    loadGT(0, 0);
    asm volatile("cp.async.commit_group;");
    loadGT(1, 1);
    asm volatile("cp.async.commit_group;");

    // ================= pass-1 epilogue: softmax -> W1 panels =================
#pragma unroll
    for (int gh = 0; gh < 2; gh++) {
        const int g = wn * 2 + gh;
        float addv[4][2]; bool isc[4][2];
#pragma unroll
        for (int nt = 0; nt < 4; nt++)
#pragma unroll
            for (int q = 0; q < 2; q++) {
                const int t = nt * 8 + lq * 2 + q;
                addv[nt][q] = beta1[g * 32 + t] + smk[t];
                isc[nt][q]  = (t < 19);
            }
#pragma unroll
        for (int mt = 0; mt < 2; mt++) {
#pragma unroll
            for (int rr = 0; rr < 2; rr++) {
                float v[4][2];
                float mc = -1e30f, mmx = -1e30f;
#pragma unroll
                for (int nt = 0; nt < 4; nt++)
#pragma unroll
                    for (int q = 0; q < 2; q++) {
                        v[nt][q] = acc1[mt][gh * 4 + nt][rr * 2 + q] + addv[nt][q];
                        if (isc[nt][q]) mc = fmaxf(mc, v[nt][q]);
                        else            mmx = fmaxf(mmx, v[nt][q]);
                    }
                mc  = fmaxf(mc,  __shfl_xor_sync(0xffffffffu, mc, 1));
                mc  = fmaxf(mc,  __shfl_xor_sync(0xffffffffu, mc, 2));
                mmx = fmaxf(mmx, __shfl_xor_sync(0xffffffffu, mmx, 1));
                mmx = fmaxf(mmx, __shfl_xor_sync(0xffffffffu, mmx, 2));

                float e[4][2];
                float sc = 0.f, sm = 0.f;
#pragma unroll
                for (int nt = 0; nt < 4; nt++)
#pragma unroll
                    for (int q = 0; q < 2; q++) {
                        const float ev = __expf(v[nt][q] - (isc[nt][q] ? mc : mmx));
                        e[nt][q] = ev;
                        if (isc[nt][q]) sc += ev; else sm += ev;
                    }
                sc += __shfl_xor_sync(0xffffffffu, sc, 1);
                sc += __shfl_xor_sync(0xffffffffu, sc, 2);
                sm += __shfl_xor_sync(0xffffffffu, sm, 1);
                sm += __shfl_xor_sync(0xffffffffu, sm, 2);
                const float ic = 1.f / sc, im = 1.f / sm;

                const int r_loc = wm * 32 + mt * 16 + (lane >> 2) + rr * 8;
                const uint32_t pbase = W1P + g * 8192;
#pragma unroll
                for (int nt = 0; nt < 4; nt++) {
                    const float w0 = e[nt][0] * (isc[nt][0] ? ic : im);
                    const float w1 = e[nt][1] * (isc[nt][1] ? ic : im);
                    const uint32_t byte = (uint32_t)r_loc * 64 + (uint32_t)(nt * 8 + lq * 2) * 2;
                    const uint32_t hh = pk2(w0, w1);
                    asm volatile("st.shared.b32 [%0], %1;"
                                 :: "r"(pbase + sw128(byte)), "r"(hh));
                }
            }
        }
    }
    __syncthreads();   // W1 panels visible to all warps

    // ================= pass 2: W1 @ GT^T, two N-halves =================
#pragma unroll 1
    for (int h = 0; h < 2; h++) {
        float acc2[2][4][4];
#pragma unroll
        for (int i = 0; i < 2; i++)
#pragma unroll
            for (int j = 0; j < 4; j++)
#pragma unroll
                for (int r = 0; r < 4; r++) acc2[i][j][r] = 0.f;

#pragma unroll 1
        for (int k2 = 0; k2 < 8; k2++) {
            const int gidx = h * 8 + k2;
            asm volatile("cp.async.wait_group 1;");
            __syncthreads();
            if (gidx + 2 < 16) loadGT((gidx + 2) % 3, gidx + 2);
            asm volatile("cp.async.commit_group;");

            const uint32_t aS = W1P + k2 * 8192;
            const uint32_t bS = B1S + (gidx % 3) * 8192;
#pragma unroll
            for (int kk = 0; kk < 2; kk++) {
                uint32_t a[2][4], bfr[2][4];
#pragma unroll
                for (int mt = 0; mt < 2; mt++) {
                    uint32_t byte = (uint32_t)(wm * 32 + mt * 16 + a_row) * 64
                                  + (uint32_t)(kk * 16 + a_k8) * 2;
                    uint32_t ad = aS + sw128(byte);
                    asm volatile(
                        "ldmatrix.sync.aligned.m8n8.x4.shared.b16 {%0,%1,%2,%3}, [%4];"
                        : "=r"(a[mt][0]), "=r"(a[mt][1]), "=r"(a[mt][2]), "=r"(a[mt][3])
                        : "r"(ad));
                }
#pragma unroll
                for (int np = 0; np < 2; np++) {
                    uint32_t byte = (uint32_t)(wn * 32 + np * 16 + b_row) * 64
                                  + (uint32_t)(kk * 16 + b_k8) * 2;
                    uint32_t bd = bS + sw128(byte);
                    asm volatile(
                        "ldmatrix.sync.aligned.m8n8.x4.shared.b16 {%0,%1,%2,%3}, [%4];"
                        : "=r"(bfr[np][0]), "=r"(bfr[np][1]), "=r"(bfr[np][2]), "=r"(bfr[np][3])
                        : "r"(bd));
                }
#pragma unroll
                for (int mt = 0; mt < 2; mt++)
#pragma unroll
                    for (int nt = 0; nt < 4; nt++) {
                        const uint32_t b0 = bfr[nt >> 1][(nt & 1) * 2];
                        const uint32_t b1v = bfr[nt >> 1][(nt & 1) * 2 + 1];
                        asm volatile(
                            "mma.sync.aligned.m16n8k16.row.col.f32.bf16.bf16.f32 "
                            "{%0,%1,%2,%3}, {%4,%5,%6,%7}, {%8,%9}, {%0,%1,%2,%3};"
                            : "+f"(acc2[mt][nt][0]), "+f"(acc2[mt][nt][1]),
                              "+f"(acc2[mt][nt][2]), "+f"(acc2[mt][nt][3])
                            : "r"(a[mt][0]), "r"(a[mt][1]), "r"(a[mt][2]), "r"(a[mt][3]),
                              "r"(b0), "r"(b1v));
                    }
            }
            __syncthreads();
        }

        // ---- epilogue half h: softmax2 + column accumulation ----
        float addv[4][2]; bool isc[4][2];
#pragma unroll
        for (int nt = 0; nt < 4; nt++)
#pragma unroll
            for (int q = 0; q < 2; q++) {
                const int t = nt * 8 + lq * 2 + q;
                addv[nt][q] = beta2[h * 128 + wn * 32 + t] + smk[t];
                isc[nt][q]  = (t < 19);
            }
        float colacc[4][2];
#pragma unroll
        for (int nt = 0; nt < 4; nt++) { colacc[nt][0] = 0.f; colacc[nt][1] = 0.f; }

#pragma unroll
        for (int mt = 0; mt < 2; mt++) {
#pragma unroll
            for (int rr = 0; rr < 2; rr++) {
                float v[4][2];
                float mc = -1e30f, mmx = -1e30f;
#pragma unroll
                for (int nt = 0; nt < 4; nt++)
#pragma unroll
                    for (int q = 0; q < 2; q++) {
                        v[nt][q] = acc2[mt][nt][rr * 2 + q] + addv[nt][q];
                        if (isc[nt][q]) mc = fmaxf(mc, v[nt][q]);
                        else            mmx = fmaxf(mmx, v[nt][q]);
                    }
                mc  = fmaxf(mc,  __shfl_xor_sync(0xffffffffu, mc, 1));
                mc  = fmaxf(mc,  __shfl_xor_sync(0xffffffffu, mc, 2));
                mmx = fmaxf(mmx, __shfl_xor_sync(0xffffffffu, mmx, 1));
                mmx = fmaxf(mmx, __shfl_xor_sync(0xffffffffu, mmx, 2));

                float e[4][2];
                float sc = 0.f, sm = 0.f;
#pragma unroll
                for (int nt = 0; nt < 4; nt++)
#pragma unroll
                    for (int q = 0; q < 2; q++) {
                        const float ev = __expf(v[nt][q] - (isc[nt][q] ? mc : mmx));
                        e[nt][q] = ev;
                        if (isc[nt][q]) sc += ev; else sm += ev;
                    }
                sc += __shfl_xor_sync(0xffffffffu, sc, 1);
                sc += __shfl_xor_sync(0xffffffffu, sc, 2);
                sm += __shfl_xor_sync(0xffffffffu, sm, 1);
                sm += __shfl_xor_sync(0xffffffffu, sm, 2);
                const float ic = 1.f / sc, im = 1.f / sm;
#pragma unroll
                for (int nt = 0; nt < 4; nt++)
#pragma unroll
                    for (int q = 0; q < 2; q++)
                        colacc[nt][q] += e[nt][q] * (isc[nt][q] ? ic : im);
            }
        }
#pragma unroll
        for (int st = 4; st < 32; st <<= 1)
#pragma unroll
            for (int nt = 0; nt < 4; nt++) {
                colacc[nt][0] += __shfl_xor_sync(0xffffffffu, colacc[nt][0], st);
                colacc[nt][1] += __shfl_xor_sync(0xffffffffu, colacc[nt][1], st);
            }
        if (lane < 4) {
#pragma unroll
            for (int nt = 0; nt < 4; nt++) {
                spart[wm][h * 128 + wn * 32 + nt * 8 + lane * 2]     = colacc[nt][0];
                spart[wm][h * 128 + wn * 32 + nt * 8 + lane * 2 + 1] = colacc[nt][1];
            }
        }
    }

    __syncthreads();
    if (tid < NP)
        part[(size_t)tile * NP + tid] =
            spart[0][tid] + spart[1][tid] + spart[2][tid] + spart[3][tid];
}

// ===================================================================
// final: Wsum = sum of 16 tile parts; out = Wsum . VWo / pmsum + S*bo/pmsum
// ===================================================================
__global__ void final_kernel(const float* __restrict__ cbo, const float* __restrict__ mbo,
                             float* __restrict__ out)
{
    __shared__ float ws[NP];
    const int b = blockIdx.x, tid = threadIdx.x;
    if (tid < NP) {
        float s = 0.f;
#pragma unroll
        for (int p = 0; p < 16; p++) s += g_part[(size_t)(b * 16 + p) * NP + tid];
        ws[tid] = s;
    }
    __syncthreads();
    const int c = tid;   // 512 threads
    float oc = 0.f, om = 0.f;
#pragma unroll 1
    for (int g = 0; g < 8; g++) {
#pragma unroll
        for (int t = 0; t < 19; t++) oc += ws[g * 32 + t] * g_VW[(size_t)(g * 32 + t) * 512 + c];
#pragma unroll
        for (int t = 19; t < 29; t++) om += ws[g * 32 + t] * g_VW[(size_t)(g * 32 + t) * 512 + c];
    }
    const float invp = 1.f / g_pmsum[b];
    oc = (oc + 2048.f * cbo[c]) * invp;
    om = (om + 2048.f * mbo[c]) * invp;
    out[b * 512 + c] = oc;
    out[BATCH * 512 + b * 512 + c] = oc - om;
}

// ===================================================================
extern "C" void kernel_launch(void* const* d_in, const int* in_sizes, int n_in,
                              void* d_out, int out_size)
{
    const float* emb   = (const float*)d_in[0];
    const int*   emask = (const int*)d_in[1];
    const int*   pmask = (const int*)d_in[2];
    // d_in[3] frame_mask cancels in softmax — unused
    const int*   cmask = (const int*)d_in[4];
    const int*   mmask = (const int*)d_in[5];
    const float* W_lin = (const float*)d_in[6];
    const float* b_lin = (const float*)d_in[7];
    const float* ctab  = (const float*)d_in[8];
    const float* mtab  = (const float*)d_in[9];
    const float* cWq = (const float*)d_in[10]; const float* cbq = (const float*)d_in[11];
    const float* cWk = (const float*)d_in[12]; const float* cbk = (const float*)d_in[13];
    const float* cWv = (const float*)d_in[14]; const float* cbv = (const float*)d_in[15];
    const float* cWo = (const float*)d_in[16]; const float* cbo = (const float*)d_in[17];
    const float* mWq = (const float*)d_in[18]; const float* mbq = (const float*)d_in[19];
    const float* mWk = (const float*)d_in[20]; const float* mbk = (const float*)d_in[21];
    const float* mWv = (const float*)d_in[22]; const float* mbv = (const float*)d_in[23];
    const float* mWo = (const float*)d_in[24]; const float* mbo = (const float*)d_in[25];
    float* out = (float*)d_out;

    __nv_bfloat16 *pP1T, *pGT;
    float *pbeta1, *pbeta2, *pPart;
    cudaGetSymbolAddress((void**)&pP1T,   g_P1T);
    cudaGetSymbolAddress((void**)&pGT,    g_GT);
    cudaGetSymbolAddress((void**)&pbeta1, g_beta1);
    cudaGetSymbolAddress((void**)&pbeta2, g_beta2);
    cudaGetSymbolAddress((void**)&pPart,  g_part);

    cudaFuncSetAttribute((const void*)fused_all,
                         cudaFuncAttributeMaxDynamicSharedMemorySize, SMEM_FUSED);
    cudaFuncSetAttribute((const void*)prep_d,
                         cudaFuncAttributeMaxDynamicSharedMemorySize, PREPD_SMEM);

    // prep chain (4 launches, by dependency level)
    prep_ab<<<94, 512>>>(ctab, mtab, cWk, cbk, cWv, cbv, mWk, mbk, mWv, mbv,
                         b_lin, cWq, cbq, mWq, mbq, cbo, mbo, emask, pmask);
    prep_b<<<768, 512>>>(cWq, mWq, cWo, mWo);
    prep_c<<<384, 512>>>(cWq, mWq, W_lin);
    prep_d<<<9, 256, PREPD_SMEM>>>();

    // fused pass 1 + pass 2
    fused_all<<<512, 512, SMEM_FUSED>>>(emb, pP1T, pGT, pbeta1, pbeta2,
                                        cmask, mmask, pPart);

    final_kernel<<<BATCH, 512>>>(cbo, mbo, out);
}